// round 3
// baseline (speedup 1.0000x reference)
#include <cuda_runtime.h>
#include <math.h>

#define Bb 4
#define Tt 2048
#define Cc 1024
#define Hh 16
#define Dd 64
#define Mm (Bb*Tt)   /* 8192 rows */

// Scratch (device globals: allocation-free rule)
__device__ float g_q[Mm*Cc];
__device__ float g_k[Mm*Cc];
__device__ float g_v[Mm*Cc];
__device__ float g_att[Mm*Cc];

// ---------------------------------------------------------------------------
// GEMM: C[m][n] = sum_k A[m][k] * W[n][k]   (A: [Mm,1024], W: [1024,1024])
// Optional epilogue: C = (1-lamb)*C + lamb*mixsrc  (value-residual mix)
// CTA tile 128x64, BK=16, 256 threads, 8x4 micro-tile.
// ---------------------------------------------------------------------------
__global__ __launch_bounds__(256) void gemm_kernel(
    const float* __restrict__ A, const float* __restrict__ W,
    float* __restrict__ Cout, const float* __restrict__ mixsrc,
    const float* __restrict__ lambp, int domix)
{
    __shared__ float As[16][128];
    __shared__ float Bs[16][64];

    const int tid = threadIdx.x;
    const int tx = tid & 15;          // 0..15  -> 4 cols
    const int ty = tid >> 4;          // 0..15  -> 8 rows
    const int row0 = blockIdx.x * 128;
    const int col0 = blockIdx.y * 64;

    float acc[8][4];
    #pragma unroll
    for (int i = 0; i < 8; i++)
        #pragma unroll
        for (int j = 0; j < 4; j++) acc[i][j] = 0.f;

    for (int k0 = 0; k0 < Cc; k0 += 16) {
        #pragma unroll
        for (int l = 0; l < 2; l++) {
            int fi = tid + 256 * l;           // 0..511 float4s
            int r  = fi >> 2;
            int kq = fi & 3;
            float4 a = *(const float4*)(A + (size_t)(row0 + r) * Cc + k0 + kq * 4);
            As[kq*4+0][r] = a.x; As[kq*4+1][r] = a.y;
            As[kq*4+2][r] = a.z; As[kq*4+3][r] = a.w;
        }
        {
            int r  = tid >> 2;                // 0..63
            int kq = tid & 3;
            float4 b = *(const float4*)(W + (size_t)(col0 + r) * Cc + k0 + kq * 4);
            Bs[kq*4+0][r] = b.x; Bs[kq*4+1][r] = b.y;
            Bs[kq*4+2][r] = b.z; Bs[kq*4+3][r] = b.w;
        }
        __syncthreads();

        #pragma unroll
        for (int kk = 0; kk < 16; kk++) {
            float4 bv = *(const float4*)&Bs[kk][tx * 4];
            float4 a0 = *(const float4*)&As[kk][ty * 8];
            float4 a1 = *(const float4*)&As[kk][ty * 8 + 4];
            float av[8] = {a0.x, a0.y, a0.z, a0.w, a1.x, a1.y, a1.z, a1.w};
            float bb[4] = {bv.x, bv.y, bv.z, bv.w};
            #pragma unroll
            for (int i = 0; i < 8; i++)
                #pragma unroll
                for (int j = 0; j < 4; j++)
                    acc[i][j] += av[i] * bb[j];
        }
        __syncthreads();
    }

    float lam = 0.f;
    if (domix) lam = *lambp;

    #pragma unroll
    for (int i = 0; i < 8; i++) {
        int m = row0 + ty * 8 + i;
        float4 o = make_float4(acc[i][0], acc[i][1], acc[i][2], acc[i][3]);
        if (domix) {
            float4 vr = *(const float4*)(mixsrc + (size_t)m * Cc + col0 + tx * 4);
            o.x = (1.f - lam) * o.x + lam * vr.x;
            o.y = (1.f - lam) * o.y + lam * vr.y;
            o.z = (1.f - lam) * o.z + lam * vr.z;
            o.w = (1.f - lam) * o.w + lam * vr.w;
        }
        *(float4*)(Cout + (size_t)m * Cc + col0 + tx * 4) = o;
    }
}

// ---------------------------------------------------------------------------
// RMSNorm (over D=64 per head) + RoPE, in place on q or k (blockIdx.y selects)
// One warp per (b,t,h) row; lane j handles pair (d=j, d=j+32).
// Trig computed in double precision of the fp32-quantized phase to pin the
// tables to the reference's float32 cos/sin within ~1 ulp.
// ---------------------------------------------------------------------------
__global__ __launch_bounds__(256) void rmsrope_kernel(float* __restrict__ q,
                                                      float* __restrict__ k)
{
    float* ptr = (blockIdx.y == 0) ? q : k;
    const int warp = threadIdx.x >> 5;
    const int lane = threadIdx.x & 31;
    const int row  = blockIdx.x * 8 + warp;            // < B*T*H = 131072
    const int t    = (row / Hh) % Tt;

    float* base = ptr + (size_t)row * 64;
    float x1 = base[lane];
    float x2 = base[lane + 32];

    float ss = x1 * x1 + x2 * x2;
    #pragma unroll
    for (int off = 16; off; off >>= 1)
        ss += __shfl_xor_sync(0xffffffffu, ss, off);

    float r = rsqrtf(ss * (1.0f / 64.0f) + 1.1920929e-7f);

    // inv_freq = 10000^(-lane/32), correctly rounded to fp32.
    double invf_d = exp2(-(double)lane * (13.287712379549449 / 32.0));
    float  invf   = (float)invf_d;
    float  fr     = __fmul_rn((float)t, invf);   // fp32 phase, like reference
    float  c      = (float)cos((double)fr);
    float  s      = (float)sin((double)fr);

    float n1 = x1 * r, n2 = x2 * r;
    base[lane]      = n1 * c + n2 * s;
    base[lane + 32] = n2 * c - n1 * s;
}

// ---------------------------------------------------------------------------
// Flash attention, fp32, causal. One CTA = one (b,h) x one 64-query block.
// Dynamic smem 64KB: QsT[d][i], KsT[d][j], Vs[j][d], Ps[i][j] (no aliasing).
// ---------------------------------------------------------------------------
__global__ __launch_bounds__(256) void flash_kernel(
    const float* __restrict__ Q, const float* __restrict__ K,
    const float* __restrict__ V, float* __restrict__ O)
{
    extern __shared__ float smem[];
    float* QsT = smem;            // [64][64] d-major
    float* KsT = smem + 4096;     // [64][64] d-major
    float* Vs  = smem + 8192;     // [64][64] j-major
    float* Ps  = smem + 12288;    // [64][64] i-major

    const int tid = threadIdx.x;
    const int tx = tid & 15;   // key cols / d cols (x4)
    const int ty = tid >> 4;   // query rows (x4)
    const int qblk = gridDim.x - 1 - blockIdx.x;   // heavy blocks first
    const int bh = blockIdx.y;
    const int b = bh >> 4, h = bh & 15;
    const size_t headoff = ((size_t)b * Tt) * Cc + (size_t)h * Dd;

    // Load Q block transposed (d-major), pre-scaled by 1/sqrt(D)=0.125
    #pragma unroll
    for (int l = 0; l < 4; l++) {
        int fi = tid + 256 * l;          // 0..1023 float4s
        int rr = fi >> 4;                // 0..63 query row
        int dq = fi & 15;                // 0..15 d-quad
        float4 a = *(const float4*)(Q + headoff + (size_t)(qblk * 64 + rr) * Cc + dq * 4);
        QsT[(dq*4+0)*64 + rr] = a.x * 0.125f;
        QsT[(dq*4+1)*64 + rr] = a.y * 0.125f;
        QsT[(dq*4+2)*64 + rr] = a.z * 0.125f;
        QsT[(dq*4+3)*64 + rr] = a.w * 0.125f;
    }

    float m[4], lsum[4], o[4][4];
    #pragma unroll
    for (int r = 0; r < 4; r++) {
        m[r] = -1e30f; lsum[r] = 0.f;
        #pragma unroll
        for (int c = 0; c < 4; c++) o[r][c] = 0.f;
    }

    for (int kb = 0; kb <= qblk; kb++) {
        __syncthreads();   // prior iteration fully consumed K/V tiles
        #pragma unroll
        for (int l = 0; l < 4; l++) {
            int fi = tid + 256 * l;
            int rr = fi >> 4;
            int dq = fi & 15;
            size_t goff = headoff + (size_t)(kb * 64 + rr) * Cc + dq * 4;
            float4 kv = *(const float4*)(K + goff);
            KsT[(dq*4+0)*64 + rr] = kv.x;
            KsT[(dq*4+1)*64 + rr] = kv.y;
            KsT[(dq*4+2)*64 + rr] = kv.z;
            KsT[(dq*4+3)*64 + rr] = kv.w;
            float4 vv = *(const float4*)(V + goff);
            *(float4*)&Vs[rr * 64 + dq * 4] = vv;
        }
        __syncthreads();

        float s[4][4];
        #pragma unroll
        for (int r = 0; r < 4; r++)
            #pragma unroll
            for (int c = 0; c < 4; c++) s[r][c] = 0.f;

        #pragma unroll 16
        for (int d = 0; d < 64; d++) {
            float4 a  = *(const float4*)&QsT[d * 64 + ty * 4];
            float4 bq = *(const float4*)&KsT[d * 64 + tx * 4];
            float av[4] = {a.x, a.y, a.z, a.w};
            float bv[4] = {bq.x, bq.y, bq.z, bq.w};
            #pragma unroll
            for (int r = 0; r < 4; r++)
                #pragma unroll
                for (int c = 0; c < 4; c++)
                    s[r][c] += av[r] * bv[c];
        }

        if (kb == qblk) {
            #pragma unroll
            for (int r = 0; r < 4; r++)
                #pragma unroll
                for (int c = 0; c < 4; c++)
                    if (tx * 4 + c > ty * 4 + r) s[r][c] = -1e30f;
        }

        #pragma unroll
        for (int r = 0; r < 4; r++) {
            float rm = fmaxf(fmaxf(s[r][0], s[r][1]), fmaxf(s[r][2], s[r][3]));
            #pragma unroll
            for (int off = 8; off; off >>= 1)
                rm = fmaxf(rm, __shfl_xor_sync(0xffffffffu, rm, off, 16));
            float mn = fmaxf(m[r], rm);
            float alpha = __expf(m[r] - mn);
            float p0 = __expf(s[r][0] - mn);
            float p1 = __expf(s[r][1] - mn);
            float p2 = __expf(s[r][2] - mn);
            float p3 = __expf(s[r][3] - mn);
            float rs = p0 + p1 + p2 + p3;
            #pragma unroll
            for (int off = 8; off; off >>= 1)
                rs += __shfl_xor_sync(0xffffffffu, rs, off, 16);
            lsum[r] = lsum[r] * alpha + rs;
            m[r] = mn;
            #pragma unroll
            for (int c = 0; c < 4; c++) o[r][c] *= alpha;
            *(float4*)&Ps[(ty * 4 + r) * 64 + tx * 4] = make_float4(p0, p1, p2, p3);
        }
        __syncthreads();   // Ps fully written before any thread consumes it

        #pragma unroll 16
        for (int j = 0; j < 64; j++) {
            float4 v = *(const float4*)&Vs[j * 64 + tx * 4];
            #pragma unroll
            for (int r = 0; r < 4; r++) {
                float p = Ps[(ty * 4 + r) * 64 + j];
                o[r][0] += p * v.x;
                o[r][1] += p * v.y;
                o[r][2] += p * v.z;
                o[r][3] += p * v.w;
            }
        }
    }

    #pragma unroll
    for (int r = 0; r < 4; r++) {
        float inv = 1.0f / lsum[r];
        int qi = qblk * 64 + ty * 4 + r;
        float4 ov = make_float4(o[r][0]*inv, o[r][1]*inv, o[r][2]*inv, o[r][3]*inv);
        *(float4*)(O + headoff + (size_t)qi * Cc + tx * 4) = ov;
    }
}

// ---------------------------------------------------------------------------
__global__ void copy_kernel(const float4* __restrict__ src,
                            float4* __restrict__ dst, int n4)
{
    for (int i = blockIdx.x * blockDim.x + threadIdx.x; i < n4;
         i += gridDim.x * blockDim.x)
        dst[i] = src[i];
}

// ---------------------------------------------------------------------------
extern "C" void kernel_launch(void* const* d_in, const int* in_sizes, int n_in,
                              void* d_out, int out_size)
{
    // Runtime input-order detection via sizes:
    //   dict order:        x(8.4M), v1(8.4M), Wq, Wk, Wv, Wproj, lamb(1)
    //   alphabetical:      Wk, Wproj, Wq, Wv, lamb(1), v1(8.4M), x(8.4M)
    const float *x, *v1, *Wq, *Wk, *Wv, *Wp, *lamb;
    if (in_sizes[0] == Mm * Cc) {            // dict order
        x    = (const float*)d_in[0];
        v1   = (const float*)d_in[1];
        Wq   = (const float*)d_in[2];
        Wk   = (const float*)d_in[3];
        Wv   = (const float*)d_in[4];
        Wp   = (const float*)d_in[5];
        lamb = (const float*)d_in[6];
    } else {                                  // alphabetical order
        Wk   = (const float*)d_in[0];
        Wp   = (const float*)d_in[1];
        Wq   = (const float*)d_in[2];
        Wv   = (const float*)d_in[3];
        lamb = (const float*)d_in[4];
        v1   = (const float*)d_in[5];
        x    = (const float*)d_in[6];
    }
    float* out = (float*)d_out;

    float *q, *k, *v, *att;
    cudaGetSymbolAddress((void**)&q,   g_q);
    cudaGetSymbolAddress((void**)&k,   g_k);
    cudaGetSymbolAddress((void**)&v,   g_v);
    cudaGetSymbolAddress((void**)&att, g_att);

    dim3 ggrid(Mm / 128, Cc / 64);
    gemm_kernel<<<ggrid, 256>>>(x, Wq, q, nullptr, nullptr, 0);
    gemm_kernel<<<ggrid, 256>>>(x, Wk, k, nullptr, nullptr, 0);
    gemm_kernel<<<ggrid, 256>>>(x, Wv, v, v1, lamb, 1);

    rmsrope_kernel<<<dim3(Bb * Tt * Hh / 8, 2), 256>>>(q, k);

    cudaFuncSetAttribute(flash_kernel,
                         cudaFuncAttributeMaxDynamicSharedMemorySize, 65536);
    flash_kernel<<<dim3(Tt / 64, Bb * Hh), 256, 65536>>>(q, k, v, att);

    gemm_kernel<<<ggrid, 256>>>(att, Wp, out, nullptr, nullptr, 0);

    if (out_size >= 2 * Mm * Cc)
        copy_kernel<<<2048, 256>>>((const float4*)v1,
                                   (float4*)(out + (size_t)Mm * Cc),
                                   (Mm * Cc) / 4);
}

// round 5
// speedup vs baseline: 1.3024x; 1.3024x over previous
#include <cuda_runtime.h>
#include <math.h>

#define Bb 4
#define Tt 2048
#define Cc 1024
#define Hh 16
#define Dd 64
#define Mm (Bb*Tt)   /* 8192 rows */

// Scratch (device globals: allocation-free rule)
__device__ float g_q[Mm*Cc];
__device__ float g_k[Mm*Cc];
__device__ float g_v[Mm*Cc];
__device__ float g_att[Mm*Cc];
__device__ float g_cos[Tt*32];
__device__ float g_sin[Tt*32];

// ---------------------------------------------------------------------------
// RoPE tables: cos/sin of fr = fp32(t) * fp32(10000^(-lane/32)), computed in
// fp64 (fp64 libm is NOT substituted by --use_fast_math; fp32 sincosf IS,
// and its MUFU version has no range reduction -> garbage at fr ~ 2000 rad,
// which was the R2/R4 rel_err=0.797 failure).
// 65536 elements total; ~10us.
// ---------------------------------------------------------------------------
__global__ void rope_table_kernel(float* __restrict__ ctab,
                                  float* __restrict__ stab)
{
    int t    = blockIdx.x;
    int lane = threadIdx.x;
    float invf = (float)exp2(-(double)lane * (13.287712379549449 / 32.0));
    float fr   = __fmul_rn((float)t, invf);     // fp32 phase, like reference
    ctab[t * 32 + lane] = (float)cos((double)fr);
    stab[t * 32 + lane] = (float)sin((double)fr);
}

// ---------------------------------------------------------------------------
// GEMM: C[m][n] = sum_k A[m][k] * W[n][k]   (A: [Mm,1024], W: [1024,1024])
// Optional epilogue: C = (1-lamb)*C + lamb*mixsrc  (value-residual mix)
// CTA tile 128x64, BK=16, 256 threads, 8x4 micro-tile.
// ---------------------------------------------------------------------------
__global__ __launch_bounds__(256) void gemm_kernel(
    const float* __restrict__ A, const float* __restrict__ W,
    float* __restrict__ Cout, const float* __restrict__ mixsrc,
    const float* __restrict__ lambp, int domix)
{
    __shared__ float As[16][128];
    __shared__ float Bs[16][64];

    const int tid = threadIdx.x;
    const int tx = tid & 15;          // 0..15  -> 4 cols
    const int ty = tid >> 4;          // 0..15  -> 8 rows
    const int row0 = blockIdx.x * 128;
    const int col0 = blockIdx.y * 64;

    float acc[8][4];
    #pragma unroll
    for (int i = 0; i < 8; i++)
        #pragma unroll
        for (int j = 0; j < 4; j++) acc[i][j] = 0.f;

    for (int k0 = 0; k0 < Cc; k0 += 16) {
        #pragma unroll
        for (int l = 0; l < 2; l++) {
            int fi = tid + 256 * l;           // 0..511 float4s
            int r  = fi >> 2;
            int kq = fi & 3;
            float4 a = *(const float4*)(A + (size_t)(row0 + r) * Cc + k0 + kq * 4);
            As[kq*4+0][r] = a.x; As[kq*4+1][r] = a.y;
            As[kq*4+2][r] = a.z; As[kq*4+3][r] = a.w;
        }
        {
            int r  = tid >> 2;                // 0..63
            int kq = tid & 3;
            float4 b = *(const float4*)(W + (size_t)(col0 + r) * Cc + k0 + kq * 4);
            Bs[kq*4+0][r] = b.x; Bs[kq*4+1][r] = b.y;
            Bs[kq*4+2][r] = b.z; Bs[kq*4+3][r] = b.w;
        }
        __syncthreads();

        #pragma unroll
        for (int kk = 0; kk < 16; kk++) {
            float4 bv = *(const float4*)&Bs[kk][tx * 4];
            float4 a0 = *(const float4*)&As[kk][ty * 8];
            float4 a1 = *(const float4*)&As[kk][ty * 8 + 4];
            float av[8] = {a0.x, a0.y, a0.z, a0.w, a1.x, a1.y, a1.z, a1.w};
            float bb[4] = {bv.x, bv.y, bv.z, bv.w};
            #pragma unroll
            for (int i = 0; i < 8; i++)
                #pragma unroll
                for (int j = 0; j < 4; j++)
                    acc[i][j] += av[i] * bb[j];
        }
        __syncthreads();
    }

    float lam = 0.f;
    if (domix) lam = *lambp;

    #pragma unroll
    for (int i = 0; i < 8; i++) {
        int m = row0 + ty * 8 + i;
        float4 o = make_float4(acc[i][0], acc[i][1], acc[i][2], acc[i][3]);
        if (domix) {
            float4 vr = *(const float4*)(mixsrc + (size_t)m * Cc + col0 + tx * 4);
            o.x = (1.f - lam) * o.x + lam * vr.x;
            o.y = (1.f - lam) * o.y + lam * vr.y;
            o.z = (1.f - lam) * o.z + lam * vr.z;
            o.w = (1.f - lam) * o.w + lam * vr.w;
        }
        *(float4*)(Cout + (size_t)m * Cc + col0 + tx * 4) = o;
    }
}

// ---------------------------------------------------------------------------
// RMSNorm (over D=64 per head) + RoPE, in place on q or k (blockIdx.y selects)
// One warp per (b,t,h) row; lane j handles pair (d=j, d=j+32).
// cos/sin come from precomputed tables (L2-resident, 128x reuse per entry).
// ---------------------------------------------------------------------------
__global__ __launch_bounds__(256) void rmsrope_kernel(float* __restrict__ q,
                                                      float* __restrict__ k,
                                                      const float* __restrict__ ctab,
                                                      const float* __restrict__ stab)
{
    float* ptr = (blockIdx.y == 0) ? q : k;
    const int warp = threadIdx.x >> 5;
    const int lane = threadIdx.x & 31;
    const int row  = blockIdx.x * 8 + warp;            // < B*T*H = 131072
    const int t    = (row / Hh) % Tt;

    float* base = ptr + (size_t)row * 64;
    float x1 = base[lane];
    float x2 = base[lane + 32];

    float ss = x1 * x1 + x2 * x2;
    #pragma unroll
    for (int off = 16; off; off >>= 1)
        ss += __shfl_xor_sync(0xffffffffu, ss, off);

    float r = rsqrtf(ss * (1.0f / 64.0f) + 1.1920929e-7f);

    float c = __ldg(&ctab[t * 32 + lane]);
    float s = __ldg(&stab[t * 32 + lane]);

    float n1 = x1 * r, n2 = x2 * r;
    base[lane]      = n1 * c + n2 * s;
    base[lane + 32] = n2 * c - n1 * s;
}

// ---------------------------------------------------------------------------
// Flash attention, fp32, causal. One CTA = one (b,h) x one 64-query block.
// Dynamic smem 64KB: QsT[d][i], KsT[d][j], Vs[j][d], Ps[i][j] (no aliasing).
// ---------------------------------------------------------------------------
__global__ __launch_bounds__(256) void flash_kernel(
    const float* __restrict__ Q, const float* __restrict__ K,
    const float* __restrict__ V, float* __restrict__ O)
{
    extern __shared__ float smem[];
    float* QsT = smem;            // [64][64] d-major
    float* KsT = smem + 4096;     // [64][64] d-major
    float* Vs  = smem + 8192;     // [64][64] j-major
    float* Ps  = smem + 12288;    // [64][64] i-major

    const int tid = threadIdx.x;
    const int tx = tid & 15;   // key cols / d cols (x4)
    const int ty = tid >> 4;   // query rows (x4)
    const int qblk = gridDim.x - 1 - blockIdx.x;   // heavy blocks first
    const int bh = blockIdx.y;
    const int b = bh >> 4, h = bh & 15;
    const size_t headoff = ((size_t)b * Tt) * Cc + (size_t)h * Dd;

    // Load Q block transposed (d-major), pre-scaled by 1/sqrt(D)=0.125
    #pragma unroll
    for (int l = 0; l < 4; l++) {
        int fi = tid + 256 * l;          // 0..1023 float4s
        int rr = fi >> 4;                // 0..63 query row
        int dq = fi & 15;                // 0..15 d-quad
        float4 a = *(const float4*)(Q + headoff + (size_t)(qblk * 64 + rr) * Cc + dq * 4);
        QsT[(dq*4+0)*64 + rr] = a.x * 0.125f;
        QsT[(dq*4+1)*64 + rr] = a.y * 0.125f;
        QsT[(dq*4+2)*64 + rr] = a.z * 0.125f;
        QsT[(dq*4+3)*64 + rr] = a.w * 0.125f;
    }

    float m[4], lsum[4], o[4][4];
    #pragma unroll
    for (int r = 0; r < 4; r++) {
        m[r] = -1e30f; lsum[r] = 0.f;
        #pragma unroll
        for (int c = 0; c < 4; c++) o[r][c] = 0.f;
    }

    for (int kb = 0; kb <= qblk; kb++) {
        __syncthreads();   // prior iteration fully consumed K/V tiles
        #pragma unroll
        for (int l = 0; l < 4; l++) {
            int fi = tid + 256 * l;
            int rr = fi >> 4;
            int dq = fi & 15;
            size_t goff = headoff + (size_t)(kb * 64 + rr) * Cc + dq * 4;
            float4 kv = *(const float4*)(K + goff);
            KsT[(dq*4+0)*64 + rr] = kv.x;
            KsT[(dq*4+1)*64 + rr] = kv.y;
            KsT[(dq*4+2)*64 + rr] = kv.z;
            KsT[(dq*4+3)*64 + rr] = kv.w;
            float4 vv = *(const float4*)(V + goff);
            *(float4*)&Vs[rr * 64 + dq * 4] = vv;
        }
        __syncthreads();

        float s[4][4];
        #pragma unroll
        for (int r = 0; r < 4; r++)
            #pragma unroll
            for (int c = 0; c < 4; c++) s[r][c] = 0.f;

        #pragma unroll 16
        for (int d = 0; d < 64; d++) {
            float4 a  = *(const float4*)&QsT[d * 64 + ty * 4];
            float4 bq = *(const float4*)&KsT[d * 64 + tx * 4];
            float av[4] = {a.x, a.y, a.z, a.w};
            float bv[4] = {bq.x, bq.y, bq.z, bq.w};
            #pragma unroll
            for (int r = 0; r < 4; r++)
                #pragma unroll
                for (int c = 0; c < 4; c++)
                    s[r][c] += av[r] * bv[c];
        }

        if (kb == qblk) {
            #pragma unroll
            for (int r = 0; r < 4; r++)
                #pragma unroll
                for (int c = 0; c < 4; c++)
                    if (tx * 4 + c > ty * 4 + r) s[r][c] = -1e30f;
        }

        #pragma unroll
        for (int r = 0; r < 4; r++) {
            float rm = fmaxf(fmaxf(s[r][0], s[r][1]), fmaxf(s[r][2], s[r][3]));
            #pragma unroll
            for (int off = 8; off; off >>= 1)
                rm = fmaxf(rm, __shfl_xor_sync(0xffffffffu, rm, off, 16));
            float mn = fmaxf(m[r], rm);
            float alpha = __expf(m[r] - mn);
            float p0 = __expf(s[r][0] - mn);
            float p1 = __expf(s[r][1] - mn);
            float p2 = __expf(s[r][2] - mn);
            float p3 = __expf(s[r][3] - mn);
            float rs = p0 + p1 + p2 + p3;
            #pragma unroll
            for (int off = 8; off; off >>= 1)
                rs += __shfl_xor_sync(0xffffffffu, rs, off, 16);
            lsum[r] = lsum[r] * alpha + rs;
            m[r] = mn;
            #pragma unroll
            for (int c = 0; c < 4; c++) o[r][c] *= alpha;
            *(float4*)&Ps[(ty * 4 + r) * 64 + tx * 4] = make_float4(p0, p1, p2, p3);
        }
        __syncthreads();   // Ps fully written before any thread consumes it

        // PV: keys in chunks of 4, Ps read as float4 (fewer LDS per FFMA)
        #pragma unroll
        for (int j0 = 0; j0 < 64; j0 += 4) {
            float4 pr0 = *(const float4*)&Ps[(ty * 4 + 0) * 64 + j0];
            float4 pr1 = *(const float4*)&Ps[(ty * 4 + 1) * 64 + j0];
            float4 pr2 = *(const float4*)&Ps[(ty * 4 + 2) * 64 + j0];
            float4 pr3 = *(const float4*)&Ps[(ty * 4 + 3) * 64 + j0];
            float p[4][4] = {{pr0.x,pr0.y,pr0.z,pr0.w},
                             {pr1.x,pr1.y,pr1.z,pr1.w},
                             {pr2.x,pr2.y,pr2.z,pr2.w},
                             {pr3.x,pr3.y,pr3.z,pr3.w}};
            #pragma unroll
            for (int jj = 0; jj < 4; jj++) {
                float4 v = *(const float4*)&Vs[(j0 + jj) * 64 + tx * 4];
                #pragma unroll
                for (int r = 0; r < 4; r++) {
                    o[r][0] += p[r][jj] * v.x;
                    o[r][1] += p[r][jj] * v.y;
                    o[r][2] += p[r][jj] * v.z;
                    o[r][3] += p[r][jj] * v.w;
                }
            }
        }
    }

    #pragma unroll
    for (int r = 0; r < 4; r++) {
        float inv = 1.0f / lsum[r];
        int qi = qblk * 64 + ty * 4 + r;
        float4 ov = make_float4(o[r][0]*inv, o[r][1]*inv, o[r][2]*inv, o[r][3]*inv);
        *(float4*)(O + headoff + (size_t)qi * Cc + tx * 4) = ov;
    }
}

// ---------------------------------------------------------------------------
__global__ void copy_kernel(const float4* __restrict__ src,
                            float4* __restrict__ dst, int n4)
{
    for (int i = blockIdx.x * blockDim.x + threadIdx.x; i < n4;
         i += gridDim.x * blockDim.x)
        dst[i] = src[i];
}

// ---------------------------------------------------------------------------
extern "C" void kernel_launch(void* const* d_in, const int* in_sizes, int n_in,
                              void* d_out, int out_size)
{
    // Runtime input-order detection via sizes (dict vs alphabetical).
    const float *x, *v1, *Wq, *Wk, *Wv, *Wp, *lamb;
    if (in_sizes[0] == Mm * Cc) {            // dict order
        x    = (const float*)d_in[0];
        v1   = (const float*)d_in[1];
        Wq   = (const float*)d_in[2];
        Wk   = (const float*)d_in[3];
        Wv   = (const float*)d_in[4];
        Wp   = (const float*)d_in[5];
        lamb = (const float*)d_in[6];
    } else {                                  // alphabetical order
        Wk   = (const float*)d_in[0];
        Wp   = (const float*)d_in[1];
        Wq   = (const float*)d_in[2];
        Wv   = (const float*)d_in[3];
        lamb = (const float*)d_in[4];
        v1   = (const float*)d_in[5];
        x    = (const float*)d_in[6];
    }
    float* out = (float*)d_out;

    float *q, *k, *v, *att, *ctab, *stab;
    cudaGetSymbolAddress((void**)&q,    g_q);
    cudaGetSymbolAddress((void**)&k,    g_k);
    cudaGetSymbolAddress((void**)&v,    g_v);
    cudaGetSymbolAddress((void**)&att,  g_att);
    cudaGetSymbolAddress((void**)&ctab, g_cos);
    cudaGetSymbolAddress((void**)&stab, g_sin);

    rope_table_kernel<<<Tt, 32>>>(ctab, stab);

    dim3 ggrid(Mm / 128, Cc / 64);
    gemm_kernel<<<ggrid, 256>>>(x, Wq, q, nullptr, nullptr, 0);
    gemm_kernel<<<ggrid, 256>>>(x, Wk, k, nullptr, nullptr, 0);
    gemm_kernel<<<ggrid, 256>>>(x, Wv, v, v1, lamb, 1);

    rmsrope_kernel<<<dim3(Bb * Tt * Hh / 8, 2), 256>>>(q, k, ctab, stab);

    cudaFuncSetAttribute(flash_kernel,
                         cudaFuncAttributeMaxDynamicSharedMemorySize, 65536);
    flash_kernel<<<dim3(Tt / 64, Bb * Hh), 256, 65536>>>(q, k, v, att);

    gemm_kernel<<<ggrid, 256>>>(att, Wp, out, nullptr, nullptr, 0);

    if (out_size >= 2 * Mm * Cc)
        copy_kernel<<<2048, 256>>>((const float4*)v1,
                                   (float4*)(out + (size_t)Mm * Cc),
                                   (Mm * Cc) / 4);
}

// round 9
// speedup vs baseline: 1.6538x; 1.2699x over previous
#include <cuda_runtime.h>
#include <cuda_bf16.h>
#include <cstdint>
#include <math.h>

#define Bb 4
#define Tt 2048
#define Cc 1024
#define Hh 16
#define Dd 64
#define Mm (Bb*Tt)   /* 8192 rows */

// Scratch (device globals: allocation-free rule)
__device__ float g_q[Mm*Cc];
__device__ float g_k[Mm*Cc];
__device__ float g_v[Mm*Cc];
__device__ float g_att[Mm*Cc];
__device__ float g_cos[Tt*32];
__device__ float g_sin[Tt*32];

// ========================== helpers ===========================
__device__ __forceinline__ uint32_t smem_u32(const void* p)
{
    uint32_t a;
    asm("{ .reg .u64 t; cvta.to.shared.u64 t, %1; cvt.u32.u64 %0, t; }"
        : "=r"(a) : "l"(p));
    return a;
}

__device__ __forceinline__ void ldm4(uint32_t* r, uint32_t addr)
{
    asm volatile("ldmatrix.sync.aligned.m8n8.x4.shared.b16 {%0,%1,%2,%3}, [%4];"
                 : "=r"(r[0]), "=r"(r[1]), "=r"(r[2]), "=r"(r[3])
                 : "r"(addr));
}

__device__ __forceinline__ void mma16816(float* d, const uint32_t* a,
                                         uint32_t b0, uint32_t b1)
{
    asm volatile(
        "mma.sync.aligned.m16n8k16.row.col.f32.bf16.bf16.f32 "
        "{%0,%1,%2,%3}, {%4,%5,%6,%7}, {%8,%9}, {%0,%1,%2,%3};"
        : "+f"(d[0]), "+f"(d[1]), "+f"(d[2]), "+f"(d[3])
        : "r"(a[0]), "r"(a[1]), "r"(a[2]), "r"(a[3]), "r"(b0), "r"(b1));
}

__device__ __forceinline__ void split4(float4 a, uint2& hi4, uint2& lo4)
{
    __nv_bfloat16 h0 = __float2bfloat16(a.x), h1 = __float2bfloat16(a.y);
    __nv_bfloat16 h2 = __float2bfloat16(a.z), h3 = __float2bfloat16(a.w);
    __nv_bfloat16 l0 = __float2bfloat16(a.x - __bfloat162float(h0));
    __nv_bfloat16 l1 = __float2bfloat16(a.y - __bfloat162float(h1));
    __nv_bfloat16 l2 = __float2bfloat16(a.z - __bfloat162float(h2));
    __nv_bfloat16 l3 = __float2bfloat16(a.w - __bfloat162float(h3));
    unsigned short u0 = *(unsigned short*)&h0, u1 = *(unsigned short*)&h1;
    unsigned short u2 = *(unsigned short*)&h2, u3 = *(unsigned short*)&h3;
    unsigned short v0 = *(unsigned short*)&l0, v1 = *(unsigned short*)&l1;
    unsigned short v2 = *(unsigned short*)&l2, v3 = *(unsigned short*)&l3;
    hi4.x = (uint32_t)u0 | ((uint32_t)u1 << 16);
    hi4.y = (uint32_t)u2 | ((uint32_t)u3 << 16);
    lo4.x = (uint32_t)v0 | ((uint32_t)v1 << 16);
    lo4.y = (uint32_t)v2 | ((uint32_t)v3 << 16);
}

// ---------------------------------------------------------------------------
// bf16-split tensor-core GEMM (mma.sync): C[m][n] = sum_k A[m][k]*W[n][k]
// CTA 128x128, BK=32, 8 warps x (32 rows x 64 cols), padded smem (stride 40).
// hi/lo split: C += Ah*Wh + Ah*Wl + Al*Wh  (Al*Wl dropped, ~2^-16 rel).
// Optional epilogue: C = (1-lamb)*C + lamb*mixsrc.
// ---------------------------------------------------------------------------
#define SK 40   /* padded K stride in elements (32 + 8) */

__global__ __launch_bounds__(256) void gemm_mma(
    const float* __restrict__ A, const float* __restrict__ W,
    float* __restrict__ Cout, const float* __restrict__ mixsrc,
    const float* __restrict__ lambp, int domix)
{
    __shared__ __align__(16) uint16_t sAh[128*SK];
    __shared__ __align__(16) uint16_t sAl[128*SK];
    __shared__ __align__(16) uint16_t sWh[128*SK];
    __shared__ __align__(16) uint16_t sWl[128*SK];

    const int tid  = threadIdx.x;
    const int wid  = tid >> 5;
    const int lane = tid & 31;
    const int warp_r = wid & 3;      // 4 row groups of 32
    const int warp_c = wid >> 2;     // 2 col groups of 64
    const int row0 = blockIdx.x * 128;
    const int col0 = blockIdx.y * 128;

    float d[2][8][4];
    #pragma unroll
    for (int mt = 0; mt < 2; mt++)
        #pragma unroll
        for (int nt = 0; nt < 8; nt++)
            #pragma unroll
            for (int e = 0; e < 4; e++) d[mt][nt][e] = 0.f;

    // per-lane ldmatrix element offsets (x4 tiles)
    const uint32_t a_elem = (uint32_t)((warp_r*32 + (lane & 15)) * SK + (lane >> 4) * 8);
    const uint32_t b_elem = (uint32_t)((warp_c*64 + (lane & 7) + ((lane >> 4) & 1) * 8) * SK
                                       + ((lane >> 3) & 1) * 8);
    const uint32_t ah_b = smem_u32(sAh), al_b = smem_u32(sAl);
    const uint32_t wh_b = smem_u32(sWh), wl_b = smem_u32(sWl);

    for (int kb = 0; kb < 32; kb++) {
        __syncthreads();   // previous math done before overwrite
        const float* Ap = A + (size_t)row0 * Cc + kb * 32;
        const float* Wp = W + (size_t)col0 * Cc + kb * 32;
        #pragma unroll
        for (int i = 0; i < 4; i++) {
            int idx = tid + 256 * i;       // 0..1023
            int r  = idx >> 3;             // 0..127
            int cq = idx & 7;              // 0..7 float4s across K=32
            uint2 h4, l4;
            float4 av = *(const float4*)(Ap + (size_t)r * Cc + cq * 4);
            split4(av, h4, l4);
            *(uint2*)&sAh[r * SK + cq * 4] = h4;
            *(uint2*)&sAl[r * SK + cq * 4] = l4;
            float4 wv = *(const float4*)(Wp + (size_t)r * Cc + cq * 4);
            split4(wv, h4, l4);
            *(uint2*)&sWh[r * SK + cq * 4] = h4;
            *(uint2*)&sWl[r * SK + cq * 4] = l4;
        }
        __syncthreads();

        #pragma unroll
        for (int ks = 0; ks < 2; ks++) {
            uint32_t ah[2][4], al[2][4];
            #pragma unroll
            for (int mt = 0; mt < 2; mt++) {
                uint32_t off = 2u * (a_elem + (uint32_t)mt * 16 * SK + (uint32_t)ks * 16);
                ldm4(ah[mt], ah_b + off);
                ldm4(al[mt], al_b + off);
            }
            uint32_t bh[4][4], bl[4][4];
            #pragma unroll
            for (int g = 0; g < 4; g++) {
                uint32_t off = 2u * (b_elem + (uint32_t)g * 16 * SK + (uint32_t)ks * 16);
                ldm4(bh[g], wh_b + off);
                ldm4(bl[g], wl_b + off);
            }
            #pragma unroll
            for (int mt = 0; mt < 2; mt++) {
                #pragma unroll
                for (int g = 0; g < 4; g++) {
                    mma16816(d[mt][2*g],   ah[mt], bh[g][0], bh[g][1]);
                    mma16816(d[mt][2*g+1], ah[mt], bh[g][2], bh[g][3]);
                    mma16816(d[mt][2*g],   ah[mt], bl[g][0], bl[g][1]);
                    mma16816(d[mt][2*g+1], ah[mt], bl[g][2], bl[g][3]);
                    mma16816(d[mt][2*g],   al[mt], bh[g][0], bh[g][1]);
                    mma16816(d[mt][2*g+1], al[mt], bh[g][2], bh[g][3]);
                }
            }
        }
    }

    // Epilogue: write 128x128 tile; optional value-residual mix.
    const float lam = domix ? *lambp : 0.f;
    const int rbase = row0 + warp_r * 32 + (lane >> 2);
    const int cbase = col0 + warp_c * 64 + (lane & 3) * 2;
    #pragma unroll
    for (int mt = 0; mt < 2; mt++) {
        #pragma unroll
        for (int nt = 0; nt < 8; nt++) {
            int rr = rbase + mt * 16;
            int cc = cbase + nt * 8;
            float2 lo = make_float2(d[mt][nt][0], d[mt][nt][1]);
            float2 hi = make_float2(d[mt][nt][2], d[mt][nt][3]);
            if (domix) {
                float2 m0 = *(const float2*)(mixsrc + (size_t)rr * Cc + cc);
                float2 m1 = *(const float2*)(mixsrc + (size_t)(rr + 8) * Cc + cc);
                lo.x = (1.f - lam) * lo.x + lam * m0.x;
                lo.y = (1.f - lam) * lo.y + lam * m0.y;
                hi.x = (1.f - lam) * hi.x + lam * m1.x;
                hi.y = (1.f - lam) * hi.y + lam * m1.y;
            }
            *(float2*)(Cout + (size_t)rr * Cc + cc) = lo;
            *(float2*)(Cout + (size_t)(rr + 8) * Cc + cc) = hi;
        }
    }
}

// ---------------------------------------------------------------------------
// RoPE tables (fp64 trig; immune to --use_fast_math substitution).
// ---------------------------------------------------------------------------
__global__ void rope_table_kernel(float* __restrict__ ctab,
                                  float* __restrict__ stab)
{
    int t    = blockIdx.x;
    int lane = threadIdx.x;
    float invf = (float)exp2(-(double)lane * (13.287712379549449 / 32.0));
    float fr   = __fmul_rn((float)t, invf);
    ctab[t * 32 + lane] = (float)cos((double)fr);
    stab[t * 32 + lane] = (float)sin((double)fr);
}

// ---------------------------------------------------------------------------
// RMSNorm + RoPE (table-driven), in place on q or k.
// ---------------------------------------------------------------------------
__global__ __launch_bounds__(256) void rmsrope_kernel(float* __restrict__ q,
                                                      float* __restrict__ k,
                                                      const float* __restrict__ ctab,
                                                      const float* __restrict__ stab)
{
    float* ptr = (blockIdx.y == 0) ? q : k;
    const int warp = threadIdx.x >> 5;
    const int lane = threadIdx.x & 31;
    const int row  = blockIdx.x * 8 + warp;
    const int t    = (row / Hh) % Tt;

    float* base = ptr + (size_t)row * 64;
    float x1 = base[lane];
    float x2 = base[lane + 32];

    float ss = x1 * x1 + x2 * x2;
    #pragma unroll
    for (int off = 16; off; off >>= 1)
        ss += __shfl_xor_sync(0xffffffffu, ss, off);

    float r = rsqrtf(ss * (1.0f / 64.0f) + 1.1920929e-7f);
    float c = __ldg(&ctab[t * 32 + lane]);
    float s = __ldg(&stab[t * 32 + lane]);

    float n1 = x1 * r, n2 = x2 * r;
    base[lane]      = n1 * c + n2 * s;
    base[lane + 32] = n2 * c - n1 * s;
}

// ---------------------------------------------------------------------------
// Flash attention, fp32, causal (same as the 2963us passing version).
// ---------------------------------------------------------------------------
__global__ __launch_bounds__(256) void flash_kernel(
    const float* __restrict__ Q, const float* __restrict__ K,
    const float* __restrict__ V, float* __restrict__ O)
{
    extern __shared__ float smem[];
    float* QsT = smem;
    float* KsT = smem + 4096;
    float* Vs  = smem + 8192;
    float* Ps  = smem + 12288;

    const int tid = threadIdx.x;
    const int tx = tid & 15;
    const int ty = tid >> 4;
    const int qblk = gridDim.x - 1 - blockIdx.x;
    const int bh = blockIdx.y;
    const int b = bh >> 4;
    const int h = bh & 15;
    const size_t headoff = ((size_t)b * Tt) * Cc + (size_t)h * Dd;

    #pragma unroll
    for (int l = 0; l < 4; l++) {
        int fi = tid + 256 * l;
        int rr = fi >> 4;
        int dq = fi & 15;
        float4 a = *(const float4*)(Q + headoff + (size_t)(qblk * 64 + rr) * Cc + dq * 4);
        QsT[(dq*4+0)*64 + rr] = a.x * 0.125f;
        QsT[(dq*4+1)*64 + rr] = a.y * 0.125f;
        QsT[(dq*4+2)*64 + rr] = a.z * 0.125f;
        QsT[(dq*4+3)*64 + rr] = a.w * 0.125f;
    }

    float m[4], lsum[4], o[4][4];
    #pragma unroll
    for (int r = 0; r < 4; r++) {
        m[r] = -1e30f;
        lsum[r] = 0.f;
        #pragma unroll
        for (int c = 0; c < 4; c++) o[r][c] = 0.f;
    }

    for (int kb = 0; kb <= qblk; kb++) {
        __syncthreads();
        #pragma unroll
        for (int l = 0; l < 4; l++) {
            int fi = tid + 256 * l;
            int rr = fi >> 4;
            int dq = fi & 15;
            size_t goff = headoff + (size_t)(kb * 64 + rr) * Cc + dq * 4;
            float4 kv = *(const float4*)(K + goff);
            KsT[(dq*4+0)*64 + rr] = kv.x;
            KsT[(dq*4+1)*64 + rr] = kv.y;
            KsT[(dq*4+2)*64 + rr] = kv.z;
            KsT[(dq*4+3)*64 + rr] = kv.w;
            float4 vv = *(const float4*)(V + goff);
            *(float4*)&Vs[rr * 64 + dq * 4] = vv;
        }
        __syncthreads();

        float s[4][4];
        #pragma unroll
        for (int r = 0; r < 4; r++)
            #pragma unroll
            for (int c = 0; c < 4; c++) s[r][c] = 0.f;

        #pragma unroll 16
        for (int dd = 0; dd < 64; dd++) {
            float4 a  = *(const float4*)&QsT[dd * 64 + ty * 4];
            float4 bq = *(const float4*)&KsT[dd * 64 + tx * 4];
            float av[4] = {a.x, a.y, a.z, a.w};
            float bv[4] = {bq.x, bq.y, bq.z, bq.w};
            #pragma unroll
            for (int r = 0; r < 4; r++)
                #pragma unroll
                for (int c = 0; c < 4; c++)
                    s[r][c] += av[r] * bv[c];
        }

        if (kb == qblk) {
            #pragma unroll
            for (int r = 0; r < 4; r++)
                #pragma unroll
                for (int c = 0; c < 4; c++)
                    if (tx * 4 + c > ty * 4 + r) s[r][c] = -1e30f;
        }

        #pragma unroll
        for (int r = 0; r < 4; r++) {
            float rm = fmaxf(fmaxf(s[r][0], s[r][1]), fmaxf(s[r][2], s[r][3]));
            #pragma unroll
            for (int off = 8; off; off >>= 1)
                rm = fmaxf(rm, __shfl_xor_sync(0xffffffffu, rm, off, 16));
            float mn = fmaxf(m[r], rm);
            float alpha = __expf(m[r] - mn);
            float p0 = __expf(s[r][0] - mn);
            float p1 = __expf(s[r][1] - mn);
            float p2 = __expf(s[r][2] - mn);
            float p3 = __expf(s[r][3] - mn);
            float rs = p0 + p1 + p2 + p3;
            #pragma unroll
            for (int off = 8; off; off >>= 1)
                rs += __shfl_xor_sync(0xffffffffu, rs, off, 16);
            lsum[r] = lsum[r] * alpha + rs;
            m[r] = mn;
            #pragma unroll
            for (int c = 0; c < 4; c++) o[r][c] *= alpha;
            *(float4*)&Ps[(ty * 4 + r) * 64 + tx * 4] = make_float4(p0, p1, p2, p3);
        }
        __syncthreads();

        #pragma unroll
        for (int j0 = 0; j0 < 64; j0 += 4) {
            float4 pr0 = *(const float4*)&Ps[(ty * 4 + 0) * 64 + j0];
            float4 pr1 = *(const float4*)&Ps[(ty * 4 + 1) * 64 + j0];
            float4 pr2 = *(const float4*)&Ps[(ty * 4 + 2) * 64 + j0];
            float4 pr3 = *(const float4*)&Ps[(ty * 4 + 3) * 64 + j0];
            float p[4][4] = {{pr0.x, pr0.y, pr0.z, pr0.w},
                             {pr1.x, pr1.y, pr1.z, pr1.w},
                             {pr2.x, pr2.y, pr2.z, pr2.w},
                             {pr3.x, pr3.y, pr3.z, pr3.w}};
            #pragma unroll
            for (int jj = 0; jj < 4; jj++) {
                float4 v = *(const float4*)&Vs[(j0 + jj) * 64 + tx * 4];
                #pragma unroll
                for (int r = 0; r < 4; r++) {
                    o[r][0] += p[r][jj] * v.x;
                    o[r][1] += p[r][jj] * v.y;
                    o[r][2] += p[r][jj] * v.z;
                    o[r][3] += p[r][jj] * v.w;
                }
            }
        }
    }

    #pragma unroll
    for (int r = 0; r < 4; r++) {
        float inv = 1.0f / lsum[r];
        int qi = qblk * 64 + ty * 4 + r;
        float4 ov = make_float4(o[r][0]*inv, o[r][1]*inv, o[r][2]*inv, o[r][3]*inv);
        *(float4*)(O + headoff + (size_t)qi * Cc + tx * 4) = ov;
    }
}

// ---------------------------------------------------------------------------
__global__ void copy_kernel(const float4* __restrict__ src,
                            float4* __restrict__ dst, int n4)
{
    for (int i = blockIdx.x * blockDim.x + threadIdx.x; i < n4;
         i += gridDim.x * blockDim.x)
        dst[i] = src[i];
}

// ---------------------------------------------------------------------------
extern "C" void kernel_launch(void* const* d_in, const int* in_sizes, int n_in,
                              void* d_out, int out_size)
{
    const float *x, *v1, *Wq, *Wk, *Wv, *Wp, *lamb;
    if (in_sizes[0] == Mm * Cc) {            // dict order
        x    = (const float*)d_in[0];
        v1   = (const float*)d_in[1];
        Wq   = (const float*)d_in[2];
        Wk   = (const float*)d_in[3];
        Wv   = (const float*)d_in[4];
        Wp   = (const float*)d_in[5];
        lamb = (const float*)d_in[6];
    } else {                                  // alphabetical order
        Wk   = (const float*)d_in[0];
        Wp   = (const float*)d_in[1];
        Wq   = (const float*)d_in[2];
        Wv   = (const float*)d_in[3];
        lamb = (const float*)d_in[4];
        v1   = (const float*)d_in[5];
        x    = (const float*)d_in[6];
    }
    float* out = (float*)d_out;

    float *q, *k, *v, *att, *ctab, *stab;
    cudaGetSymbolAddress((void**)&q,    g_q);
    cudaGetSymbolAddress((void**)&k,    g_k);
    cudaGetSymbolAddress((void**)&v,    g_v);
    cudaGetSymbolAddress((void**)&att,  g_att);
    cudaGetSymbolAddress((void**)&ctab, g_cos);
    cudaGetSymbolAddress((void**)&stab, g_sin);

    rope_table_kernel<<<Tt, 32>>>(ctab, stab);

    dim3 ggrid(Mm / 128, Cc / 128);
    gemm_mma<<<ggrid, 256>>>(x, Wq, q, (const float*)0, (const float*)0, 0);
    gemm_mma<<<ggrid, 256>>>(x, Wk, k, (const float*)0, (const float*)0, 0);
    gemm_mma<<<ggrid, 256>>>(x, Wv, v, v1, lamb, 1);

    rmsrope_kernel<<<dim3(Bb * Tt * Hh / 8, 2), 256>>>(q, k, ctab, stab);

    cudaFuncSetAttribute(flash_kernel,
                         cudaFuncAttributeMaxDynamicSharedMemorySize, 65536);
    flash_kernel<<<dim3(Tt / 64, Bb * Hh), 256, 65536>>>(q, k, v, att);

    gemm_mma<<<ggrid, 256>>>(att, Wp, out, (const float*)0, (const float*)0, 0);

    if (out_size >= 2 * Mm * Cc)
        copy_kernel<<<2048, 256>>>((const float4*)v1,
                                   (float4*)(out + (size_t)Mm * Cc),
                                   (Mm * Cc) / 4);
}

// round 10
// speedup vs baseline: 1.8901x; 1.1429x over previous
#include <cuda_runtime.h>
#include <cuda_bf16.h>
#include <cstdint>
#include <math.h>

#define Bb 4
#define Tt 2048
#define Cc 1024
#define Hh 16
#define Dd 64
#define Mm (Bb*Tt)   /* 8192 rows */

// Scratch (device globals: allocation-free rule)
__device__ float g_q[Mm*Cc];
__device__ float g_k[Mm*Cc];
__device__ float g_v[Mm*Cc];
__device__ float g_att[Mm*Cc];
__device__ float g_cos[Tt*32];
__device__ float g_sin[Tt*32];
// bf16 hi/lo split operands (x is reused for att before the proj GEMM)
__device__ uint16_t g_xh[Mm*Cc];
__device__ uint16_t g_xl[Mm*Cc];
__device__ uint16_t g_wh[4*Cc*Cc];
__device__ uint16_t g_wl[4*Cc*Cc];

// ========================== helpers ===========================
__device__ __forceinline__ uint32_t smem_u32(const void* p)
{
    uint32_t a;
    asm("{ .reg .u64 t; cvta.to.shared.u64 t, %1; cvt.u32.u64 %0, t; }"
        : "=r"(a) : "l"(p));
    return a;
}

__device__ __forceinline__ void ldm4(uint32_t* r, uint32_t addr)
{
    asm volatile("ldmatrix.sync.aligned.m8n8.x4.shared.b16 {%0,%1,%2,%3}, [%4];"
                 : "=r"(r[0]), "=r"(r[1]), "=r"(r[2]), "=r"(r[3])
                 : "r"(addr));
}

__device__ __forceinline__ void mma16816(float* d, const uint32_t* a,
                                         uint32_t b0, uint32_t b1)
{
    asm volatile(
        "mma.sync.aligned.m16n8k16.row.col.f32.bf16.bf16.f32 "
        "{%0,%1,%2,%3}, {%4,%5,%6,%7}, {%8,%9}, {%0,%1,%2,%3};"
        : "+f"(d[0]), "+f"(d[1]), "+f"(d[2]), "+f"(d[3])
        : "r"(a[0]), "r"(a[1]), "r"(a[2]), "r"(a[3]), "r"(b0), "r"(b1));
}

__device__ __forceinline__ void cp16(uint32_t dst, const void* src)
{
    asm volatile("cp.async.cg.shared.global [%0], [%1], 16;"
                 :: "r"(dst), "l"(src));
}
#define CP_COMMIT() asm volatile("cp.async.commit_group;" ::: "memory")
#define CP_WAIT2()  asm volatile("cp.async.wait_group 2;"  ::: "memory")

__device__ __forceinline__ void split4(float4 a, uint2& hi4, uint2& lo4)
{
    __nv_bfloat16 h0 = __float2bfloat16(a.x), h1 = __float2bfloat16(a.y);
    __nv_bfloat16 h2 = __float2bfloat16(a.z), h3 = __float2bfloat16(a.w);
    __nv_bfloat16 l0 = __float2bfloat16(a.x - __bfloat162float(h0));
    __nv_bfloat16 l1 = __float2bfloat16(a.y - __bfloat162float(h1));
    __nv_bfloat16 l2 = __float2bfloat16(a.z - __bfloat162float(h2));
    __nv_bfloat16 l3 = __float2bfloat16(a.w - __bfloat162float(h3));
    unsigned short u0 = *(unsigned short*)&h0, u1 = *(unsigned short*)&h1;
    unsigned short u2 = *(unsigned short*)&h2, u3 = *(unsigned short*)&h3;
    unsigned short v0 = *(unsigned short*)&l0, v1 = *(unsigned short*)&l1;
    unsigned short v2 = *(unsigned short*)&l2, v3 = *(unsigned short*)&l3;
    hi4.x = (uint32_t)u0 | ((uint32_t)u1 << 16);
    hi4.y = (uint32_t)u2 | ((uint32_t)u3 << 16);
    lo4.x = (uint32_t)v0 | ((uint32_t)v1 << 16);
    lo4.y = (uint32_t)v2 | ((uint32_t)v3 << 16);
}

// ---------------------------------------------------------------------------
// fp32 -> (hi, lo) bf16 split, elementwise (done ONCE per tensor).
// ---------------------------------------------------------------------------
__global__ void split_kernel(const float4* __restrict__ src,
                             uint2* __restrict__ hi, uint2* __restrict__ lo,
                             int n4)
{
    int i = blockIdx.x * blockDim.x + threadIdx.x;
    if (i < n4) {
        uint2 h4, l4;
        split4(src[i], h4, l4);
        hi[i] = h4;
        lo[i] = l4;
    }
}

// ---------------------------------------------------------------------------
// bf16-split tensor-core GEMM, cp.async 4-stage pipeline.
// C[m][n] = sum_k A[m][k]*W[n][k];  C += Ah*Wh + Ah*Wl + Al*Wh.
// CTA 128x128, BK=32, 8 warps x (32 rows x 64 cols), padded smem stride 40.
// Optional epilogue: C = (1-lamb)*C + lamb*mixsrc.
// ---------------------------------------------------------------------------
#define SK 40                      /* padded K stride, elements */
#define ARR_B (128*SK*2)           /* one operand array: 10240 B */
#define STG_B (4*ARR_B)            /* stage: Ah,Al,Wh,Wl = 40960 B */
#define NSTG 4
#define GBF_SMEM (NSTG*STG_B)      /* 163840 B dynamic smem */

__global__ __launch_bounds__(256) void gemm_bf(
    const uint16_t* __restrict__ Ah, const uint16_t* __restrict__ Al,
    const uint16_t* __restrict__ Wh, const uint16_t* __restrict__ Wl,
    float* __restrict__ Cout, const float* __restrict__ mixsrc,
    const float* __restrict__ lambp, int domix)
{
    extern __shared__ __align__(16) char dsm[];
    const uint32_t sbase = smem_u32(dsm);
    const int tid  = threadIdx.x;
    const int wid  = tid >> 5;
    const int lane = tid & 31;
    const int warp_r = wid & 3;
    const int warp_c = wid >> 2;
    const int row0 = blockIdx.x * 128;
    const int col0 = blockIdx.y * 128;

    float d[2][8][4];
    #pragma unroll
    for (int mt = 0; mt < 2; mt++)
        #pragma unroll
        for (int nt = 0; nt < 8; nt++)
            #pragma unroll
            for (int e = 0; e < 4; e++) d[mt][nt][e] = 0.f;

    const uint32_t a_elem = (uint32_t)((warp_r*32 + (lane & 15)) * SK + (lane >> 4) * 8);
    const uint32_t b_elem = (uint32_t)((warp_c*64 + (lane & 7) + ((lane >> 4) & 1) * 8) * SK
                                       + ((lane >> 3) & 1) * 8);

    // cp.async per-thread chunk assignment: 512 chunks per array, 2 per thread
    const int cr0 = tid >> 2;               // row for chunk set 0 (0..63)
    const int cc0 = tid & 3;                // chunk col
    // second chunk: rows 64..127
    #define ISSUE_STAGE(st, kb)                                                   \
    do {                                                                          \
        uint32_t sb_ = sbase + (uint32_t)(st) * STG_B;                            \
        int koff_ = (kb) * 32;                                                    \
        { int r_ = cr0;                                                           \
          uint32_t doff_ = (uint32_t)(r_ * 80 + cc0 * 16);                        \
          size_t ga_ = (size_t)(row0 + r_) * Cc + koff_ + cc0 * 8;                \
          size_t gw_ = (size_t)(col0 + r_) * Cc + koff_ + cc0 * 8;                \
          cp16(sb_ + doff_,             Ah + ga_);                                \
          cp16(sb_ + ARR_B + doff_,     Al + ga_);                                \
          cp16(sb_ + 2*ARR_B + doff_,   Wh + gw_);                                \
          cp16(sb_ + 3*ARR_B + doff_,   Wl + gw_); }                              \
        { int r_ = cr0 + 64;                                                      \
          uint32_t doff_ = (uint32_t)(r_ * 80 + cc0 * 16);                        \
          size_t ga_ = (size_t)(row0 + r_) * Cc + koff_ + cc0 * 8;                \
          size_t gw_ = (size_t)(col0 + r_) * Cc + koff_ + cc0 * 8;                \
          cp16(sb_ + doff_,             Ah + ga_);                                \
          cp16(sb_ + ARR_B + doff_,     Al + ga_);                                \
          cp16(sb_ + 2*ARR_B + doff_,   Wh + gw_);                                \
          cp16(sb_ + 3*ARR_B + doff_,   Wl + gw_); }                              \
    } while (0)

    // Prologue: fill stages 0..2
    ISSUE_STAGE(0, 0); CP_COMMIT();
    ISSUE_STAGE(1, 1); CP_COMMIT();
    ISSUE_STAGE(2, 2); CP_COMMIT();

    for (int kb = 0; kb < 32; kb++) {
        CP_WAIT2();
        __syncthreads();

        if (kb + 3 < 32) {
            ISSUE_STAGE((kb + 3) & 3, kb + 3);
        }
        CP_COMMIT();

        const uint32_t sb = sbase + (uint32_t)(kb & 3) * STG_B;
        const uint32_t ah_b = sb;
        const uint32_t al_b = sb + ARR_B;
        const uint32_t wh_b = sb + 2*ARR_B;
        const uint32_t wl_b = sb + 3*ARR_B;

        #pragma unroll
        for (int ks = 0; ks < 2; ks++) {
            uint32_t ah[2][4], al[2][4];
            #pragma unroll
            for (int mt = 0; mt < 2; mt++) {
                uint32_t off = 2u * (a_elem + (uint32_t)mt * 16 * SK + (uint32_t)ks * 16);
                ldm4(ah[mt], ah_b + off);
                ldm4(al[mt], al_b + off);
            }
            uint32_t bh[4][4], bl[4][4];
            #pragma unroll
            for (int g = 0; g < 4; g++) {
                uint32_t off = 2u * (b_elem + (uint32_t)g * 16 * SK + (uint32_t)ks * 16);
                ldm4(bh[g], wh_b + off);
                ldm4(bl[g], wl_b + off);
            }
            #pragma unroll
            for (int mt = 0; mt < 2; mt++) {
                #pragma unroll
                for (int g = 0; g < 4; g++) {
                    mma16816(d[mt][2*g],   ah[mt], bh[g][0], bh[g][1]);
                    mma16816(d[mt][2*g+1], ah[mt], bh[g][2], bh[g][3]);
                    mma16816(d[mt][2*g],   ah[mt], bl[g][0], bl[g][1]);
                    mma16816(d[mt][2*g+1], ah[mt], bl[g][2], bl[g][3]);
                    mma16816(d[mt][2*g],   al[mt], bh[g][0], bh[g][1]);
                    mma16816(d[mt][2*g+1], al[mt], bh[g][2], bh[g][3]);
                }
            }
        }
        __syncthreads();
    }
    #undef ISSUE_STAGE

    // Epilogue: write 128x128 tile; optional value-residual mix.
    const float lam = domix ? *lambp : 0.f;
    const int rbase = row0 + warp_r * 32 + (lane >> 2);
    const int cbase = col0 + warp_c * 64 + (lane & 3) * 2;
    #pragma unroll
    for (int mt = 0; mt < 2; mt++) {
        #pragma unroll
        for (int nt = 0; nt < 8; nt++) {
            int rr = rbase + mt * 16;
            int cc = cbase + nt * 8;
            float2 lo = make_float2(d[mt][nt][0], d[mt][nt][1]);
            float2 hi = make_float2(d[mt][nt][2], d[mt][nt][3]);
            if (domix) {
                float2 m0 = *(const float2*)(mixsrc + (size_t)rr * Cc + cc);
                float2 m1 = *(const float2*)(mixsrc + (size_t)(rr + 8) * Cc + cc);
                lo.x = (1.f - lam) * lo.x + lam * m0.x;
                lo.y = (1.f - lam) * lo.y + lam * m0.y;
                hi.x = (1.f - lam) * hi.x + lam * m1.x;
                hi.y = (1.f - lam) * hi.y + lam * m1.y;
            }
            *(float2*)(Cout + (size_t)rr * Cc + cc) = lo;
            *(float2*)(Cout + (size_t)(rr + 8) * Cc + cc) = hi;
        }
    }
}

// ---------------------------------------------------------------------------
// RoPE tables (fp64 trig; immune to --use_fast_math substitution).
// ---------------------------------------------------------------------------
__global__ void rope_table_kernel(float* __restrict__ ctab,
                                  float* __restrict__ stab)
{
    int t    = blockIdx.x;
    int lane = threadIdx.x;
    float invf = (float)exp2(-(double)lane * (13.287712379549449 / 32.0));
    float fr   = __fmul_rn((float)t, invf);
    ctab[t * 32 + lane] = (float)cos((double)fr);
    stab[t * 32 + lane] = (float)sin((double)fr);
}

// ---------------------------------------------------------------------------
// RMSNorm + RoPE (table-driven), in place on q or k.
// ---------------------------------------------------------------------------
__global__ __launch_bounds__(256) void rmsrope_kernel(float* __restrict__ q,
                                                      float* __restrict__ k,
                                                      const float* __restrict__ ctab,
                                                      const float* __restrict__ stab)
{
    float* ptr = (blockIdx.y == 0) ? q : k;
    const int warp = threadIdx.x >> 5;
    const int lane = threadIdx.x & 31;
    const int row  = blockIdx.x * 8 + warp;
    const int t    = (row / Hh) % Tt;

    float* base = ptr + (size_t)row * 64;
    float x1 = base[lane];
    float x2 = base[lane + 32];

    float ss = x1 * x1 + x2 * x2;
    #pragma unroll
    for (int off = 16; off; off >>= 1)
        ss += __shfl_xor_sync(0xffffffffu, ss, off);

    float r = rsqrtf(ss * (1.0f / 64.0f) + 1.1920929e-7f);
    float c = __ldg(&ctab[t * 32 + lane]);
    float s = __ldg(&stab[t * 32 + lane]);

    float n1 = x1 * r, n2 = x2 * r;
    base[lane]      = n1 * c + n2 * s;
    base[lane + 32] = n2 * c - n1 * s;
}

// ---------------------------------------------------------------------------
// Flash attention, fp32, causal (proven correct; unchanged).
// ---------------------------------------------------------------------------
__global__ __launch_bounds__(256) void flash_kernel(
    const float* __restrict__ Q, const float* __restrict__ K,
    const float* __restrict__ V, float* __restrict__ O)
{
    extern __shared__ float smem[];
    float* QsT = smem;
    float* KsT = smem + 4096;
    float* Vs  = smem + 8192;
    float* Ps  = smem + 12288;

    const int tid = threadIdx.x;
    const int tx = tid & 15;
    const int ty = tid >> 4;
    const int qblk = gridDim.x - 1 - blockIdx.x;
    const int bh = blockIdx.y;
    const int b = bh >> 4;
    const int h = bh & 15;
    const size_t headoff = ((size_t)b * Tt) * Cc + (size_t)h * Dd;

    #pragma unroll
    for (int l = 0; l < 4; l++) {
        int fi = tid + 256 * l;
        int rr = fi >> 4;
        int dq = fi & 15;
        float4 a = *(const float4*)(Q + headoff + (size_t)(qblk * 64 + rr) * Cc + dq * 4);
        QsT[(dq*4+0)*64 + rr] = a.x * 0.125f;
        QsT[(dq*4+1)*64 + rr] = a.y * 0.125f;
        QsT[(dq*4+2)*64 + rr] = a.z * 0.125f;
        QsT[(dq*4+3)*64 + rr] = a.w * 0.125f;
    }

    float m[4], lsum[4], o[4][4];
    #pragma unroll
    for (int r = 0; r < 4; r++) {
        m[r] = -1e30f;
        lsum[r] = 0.f;
        #pragma unroll
        for (int c = 0; c < 4; c++) o[r][c] = 0.f;
    }

    for (int kb = 0; kb <= qblk; kb++) {
        __syncthreads();
        #pragma unroll
        for (int l = 0; l < 4; l++) {
            int fi = tid + 256 * l;
            int rr = fi >> 4;
            int dq = fi & 15;
            size_t goff = headoff + (size_t)(kb * 64 + rr) * Cc + dq * 4;
            float4 kv = *(const float4*)(K + goff);
            KsT[(dq*4+0)*64 + rr] = kv.x;
            KsT[(dq*4+1)*64 + rr] = kv.y;
            KsT[(dq*4+2)*64 + rr] = kv.z;
            KsT[(dq*4+3)*64 + rr] = kv.w;
            float4 vv = *(const float4*)(V + goff);
            *(float4*)&Vs[rr * 64 + dq * 4] = vv;
        }
        __syncthreads();

        float s[4][4];
        #pragma unroll
        for (int r = 0; r < 4; r++)
            #pragma unroll
            for (int c = 0; c < 4; c++) s[r][c] = 0.f;

        #pragma unroll 16
        for (int dd = 0; dd < 64; dd++) {
            float4 a  = *(const float4*)&QsT[dd * 64 + ty * 4];
            float4 bq = *(const float4*)&KsT[dd * 64 + tx * 4];
            float av[4] = {a.x, a.y, a.z, a.w};
            float bv[4] = {bq.x, bq.y, bq.z, bq.w};
            #pragma unroll
            for (int r = 0; r < 4; r++)
                #pragma unroll
                for (int c = 0; c < 4; c++)
                    s[r][c] += av[r] * bv[c];
        }

        if (kb == qblk) {
            #pragma unroll
            for (int r = 0; r < 4; r++)
                #pragma unroll
                for (int c = 0; c < 4; c++)
                    if (tx * 4 + c > ty * 4 + r) s[r][c] = -1e30f;
        }

        #pragma unroll
        for (int r = 0; r < 4; r++) {
            float rm = fmaxf(fmaxf(s[r][0], s[r][1]), fmaxf(s[r][2], s[r][3]));
            #pragma unroll
            for (int off = 8; off; off >>= 1)
                rm = fmaxf(rm, __shfl_xor_sync(0xffffffffu, rm, off, 16));
            float mn = fmaxf(m[r], rm);
            float alpha = __expf(m[r] - mn);
            float p0 = __expf(s[r][0] - mn);
            float p1 = __expf(s[r][1] - mn);
            float p2 = __expf(s[r][2] - mn);
            float p3 = __expf(s[r][3] - mn);
            float rs = p0 + p1 + p2 + p3;
            #pragma unroll
            for (int off = 8; off; off >>= 1)
                rs += __shfl_xor_sync(0xffffffffu, rs, off, 16);
            lsum[r] = lsum[r] * alpha + rs;
            m[r] = mn;
            #pragma unroll
            for (int c = 0; c < 4; c++) o[r][c] *= alpha;
            *(float4*)&Ps[(ty * 4 + r) * 64 + tx * 4] = make_float4(p0, p1, p2, p3);
        }
        __syncthreads();

        #pragma unroll
        for (int j0 = 0; j0 < 64; j0 += 4) {
            float4 pr0 = *(const float4*)&Ps[(ty * 4 + 0) * 64 + j0];
            float4 pr1 = *(const float4*)&Ps[(ty * 4 + 1) * 64 + j0];
            float4 pr2 = *(const float4*)&Ps[(ty * 4 + 2) * 64 + j0];
            float4 pr3 = *(const float4*)&Ps[(ty * 4 + 3) * 64 + j0];
            float p[4][4] = {{pr0.x, pr0.y, pr0.z, pr0.w},
                             {pr1.x, pr1.y, pr1.z, pr1.w},
                             {pr2.x, pr2.y, pr2.z, pr2.w},
                             {pr3.x, pr3.y, pr3.z, pr3.w}};
            #pragma unroll
            for (int jj = 0; jj < 4; jj++) {
                float4 v = *(const float4*)&Vs[(j0 + jj) * 64 + tx * 4];
                #pragma unroll
                for (int r = 0; r < 4; r++) {
                    o[r][0] += p[r][jj] * v.x;
                    o[r][1] += p[r][jj] * v.y;
                    o[r][2] += p[r][jj] * v.z;
                    o[r][3] += p[r][jj] * v.w;
                }
            }
        }
    }

    #pragma unroll
    for (int r = 0; r < 4; r++) {
        float inv = 1.0f / lsum[r];
        int qi = qblk * 64 + ty * 4 + r;
        float4 ov = make_float4(o[r][0]*inv, o[r][1]*inv, o[r][2]*inv, o[r][3]*inv);
        *(float4*)(O + headoff + (size_t)qi * Cc + tx * 4) = ov;
    }
}

// ---------------------------------------------------------------------------
__global__ void copy_kernel(const float4* __restrict__ src,
                            float4* __restrict__ dst, int n4)
{
    for (int i = blockIdx.x * blockDim.x + threadIdx.x; i < n4;
         i += gridDim.x * blockDim.x)
        dst[i] = src[i];
}

// ---------------------------------------------------------------------------
extern "C" void kernel_launch(void* const* d_in, const int* in_sizes, int n_in,
                              void* d_out, int out_size)
{
    const float *x, *v1, *Wq, *Wk, *Wv, *Wp, *lamb;
    if (in_sizes[0] == Mm * Cc) {            // dict order
        x    = (const float*)d_in[0];
        v1   = (const float*)d_in[1];
        Wq   = (const float*)d_in[2];
        Wk   = (const float*)d_in[3];
        Wv   = (const float*)d_in[4];
        Wp   = (const float*)d_in[5];
        lamb = (const float*)d_in[6];
    } else {                                  // alphabetical order
        Wk   = (const float*)d_in[0];
        Wp   = (const float*)d_in[1];
        Wq   = (const float*)d_in[2];
        Wv   = (const float*)d_in[3];
        lamb = (const float*)d_in[4];
        v1   = (const float*)d_in[5];
        x    = (const float*)d_in[6];
    }
    float* out = (float*)d_out;

    float *q, *k, *v, *att, *ctab, *stab;
    uint16_t *xh, *xl, *wh, *wl;
    cudaGetSymbolAddress((void**)&q,    g_q);
    cudaGetSymbolAddress((void**)&k,    g_k);
    cudaGetSymbolAddress((void**)&v,    g_v);
    cudaGetSymbolAddress((void**)&att,  g_att);
    cudaGetSymbolAddress((void**)&ctab, g_cos);
    cudaGetSymbolAddress((void**)&stab, g_sin);
    cudaGetSymbolAddress((void**)&xh,   g_xh);
    cudaGetSymbolAddress((void**)&xl,   g_xl);
    cudaGetSymbolAddress((void**)&wh,   g_wh);
    cudaGetSymbolAddress((void**)&wl,   g_wl);

    rope_table_kernel<<<Tt, 32>>>(ctab, stab);

    // One-time hi/lo splits
    const int nx4 = Mm * Cc / 4;            // 2,097,152
    const int nw4 = Cc * Cc / 4;            // 262,144
    split_kernel<<<(nx4 + 255) / 256, 256>>>((const float4*)x,
        (uint2*)xh, (uint2*)xl, nx4);
    split_kernel<<<(nw4 + 255) / 256, 256>>>((const float4*)Wq,
        (uint2*)(wh + 0ll*Cc*Cc), (uint2*)(wl + 0ll*Cc*Cc), nw4);
    split_kernel<<<(nw4 + 255) / 256, 256>>>((const float4*)Wk,
        (uint2*)(wh + 1ll*Cc*Cc), (uint2*)(wl + 1ll*Cc*Cc), nw4);
    split_kernel<<<(nw4 + 255) / 256, 256>>>((const float4*)Wv,
        (uint2*)(wh + 2ll*Cc*Cc), (uint2*)(wl + 2ll*Cc*Cc), nw4);
    split_kernel<<<(nw4 + 255) / 256, 256>>>((const float4*)Wp,
        (uint2*)(wh + 3ll*Cc*Cc), (uint2*)(wl + 3ll*Cc*Cc), nw4);

    cudaFuncSetAttribute(gemm_bf,
                         cudaFuncAttributeMaxDynamicSharedMemorySize, GBF_SMEM);
    dim3 ggrid(Mm / 128, Cc / 128);
    gemm_bf<<<ggrid, 256, GBF_SMEM>>>(xh, xl, wh + 0ll*Cc*Cc, wl + 0ll*Cc*Cc,
                                      q, (const float*)0, (const float*)0, 0);
    gemm_bf<<<ggrid, 256, GBF_SMEM>>>(xh, xl, wh + 1ll*Cc*Cc, wl + 1ll*Cc*Cc,
                                      k, (const float*)0, (const float*)0, 0);
    gemm_bf<<<ggrid, 256, GBF_SMEM>>>(xh, xl, wh + 2ll*Cc*Cc, wl + 2ll*Cc*Cc,
                                      v, v1, lamb, 1);

    rmsrope_kernel<<<dim3(Bb * Tt * Hh / 8, 2), 256>>>(q, k, ctab, stab);

    cudaFuncSetAttribute(flash_kernel,
                         cudaFuncAttributeMaxDynamicSharedMemorySize, 65536);
    flash_kernel<<<dim3(Tt / 64, Bb * Hh), 256, 65536>>>(q, k, v, att);

    // att -> split (x buffers are dead now), then proj GEMM
    split_kernel<<<(nx4 + 255) / 256, 256>>>((const float4*)att,
        (uint2*)xh, (uint2*)xl, nx4);
    gemm_bf<<<ggrid, 256, GBF_SMEM>>>(xh, xl, wh + 3ll*Cc*Cc, wl + 3ll*Cc*Cc,
                                      out, (const float*)0, (const float*)0, 0);

    if (out_size >= 2 * Mm * Cc)
        copy_kernel<<<2048, 256>>>((const float4*)v1,
                                   (float4*)(out + (size_t)Mm * Cc),
                                   (Mm * Cc) / 4);
}

// round 12
// speedup vs baseline: 3.2716x; 1.7309x over previous
#include <cuda_runtime.h>
#include <cuda_bf16.h>
#include <cstdint>
#include <math.h>

#define Bb 4
#define Tt 2048
#define Cc 1024
#define Hh 16
#define Dd 64
#define Mm (Bb*Tt)   /* 8192 rows */

// Scratch (device globals: allocation-free rule)
__device__ float g_q[Mm*Cc];
__device__ float g_k[Mm*Cc];
__device__ float g_v[Mm*Cc];
__device__ float g_cos[Tt*32];
__device__ float g_sin[Tt*32];
// bf16 hi/lo split operands
__device__ uint16_t g_xh[Mm*Cc];   // x split; later reused for attention output
__device__ uint16_t g_xl[Mm*Cc];
__device__ uint16_t g_wh[4*Cc*Cc];
__device__ uint16_t g_wl[4*Cc*Cc];
__device__ uint16_t g_qh[Mm*Cc];
__device__ uint16_t g_ql[Mm*Cc];
__device__ uint16_t g_kh[Mm*Cc];
__device__ uint16_t g_kl[Mm*Cc];
__device__ uint16_t g_vh[Mm*Cc];
__device__ uint16_t g_vl[Mm*Cc];

// ========================== helpers ===========================
__device__ __forceinline__ uint32_t smem_u32(const void* p)
{
    uint32_t a;
    asm("{ .reg .u64 t; cvta.to.shared.u64 t, %1; cvt.u32.u64 %0, t; }"
        : "=r"(a) : "l"(p));
    return a;
}

__device__ __forceinline__ void ldm4(uint32_t* r, uint32_t addr)
{
    asm volatile("ldmatrix.sync.aligned.m8n8.x4.shared.b16 {%0,%1,%2,%3}, [%4];"
                 : "=r"(r[0]), "=r"(r[1]), "=r"(r[2]), "=r"(r[3])
                 : "r"(addr));
}

__device__ __forceinline__ void ldm4t(uint32_t* r, uint32_t addr)
{
    asm volatile("ldmatrix.sync.aligned.m8n8.x4.trans.shared.b16 {%0,%1,%2,%3}, [%4];"
                 : "=r"(r[0]), "=r"(r[1]), "=r"(r[2]), "=r"(r[3])
                 : "r"(addr));
}

__device__ __forceinline__ void mma16816(float* d, const uint32_t* a,
                                         uint32_t b0, uint32_t b1)
{
    asm volatile(
        "mma.sync.aligned.m16n8k16.row.col.f32.bf16.bf16.f32 "
        "{%0,%1,%2,%3}, {%4,%5,%6,%7}, {%8,%9}, {%0,%1,%2,%3};"
        : "+f"(d[0]), "+f"(d[1]), "+f"(d[2]), "+f"(d[3])
        : "r"(a[0]), "r"(a[1]), "r"(a[2]), "r"(a[3]), "r"(b0), "r"(b1));
}

__device__ __forceinline__ void cp16(uint32_t dst, const void* src)
{
    asm volatile("cp.async.cg.shared.global [%0], [%1], 16;"
                 :: "r"(dst), "l"(src));
}
#define CP_COMMIT() asm volatile("cp.async.commit_group;" ::: "memory")
#define CP_WAIT2()  asm volatile("cp.async.wait_group 2;"  ::: "memory")
#define CP_WAIT1()  asm volatile("cp.async.wait_group 1;"  ::: "memory")
#define CP_WAIT0()  asm volatile("cp.async.wait_group 0;"  ::: "memory")

__device__ __forceinline__ void split4(float4 a, uint2& hi4, uint2& lo4)
{
    __nv_bfloat16 h0 = __float2bfloat16(a.x), h1 = __float2bfloat16(a.y);
    __nv_bfloat16 h2 = __float2bfloat16(a.z), h3 = __float2bfloat16(a.w);
    __nv_bfloat16 l0 = __float2bfloat16(a.x - __bfloat162float(h0));
    __nv_bfloat16 l1 = __float2bfloat16(a.y - __bfloat162float(h1));
    __nv_bfloat16 l2 = __float2bfloat16(a.z - __bfloat162float(h2));
    __nv_bfloat16 l3 = __float2bfloat16(a.w - __bfloat162float(h3));
    unsigned short u0 = *(unsigned short*)&h0, u1 = *(unsigned short*)&h1;
    unsigned short u2 = *(unsigned short*)&h2, u3 = *(unsigned short*)&h3;
    unsigned short v0 = *(unsigned short*)&l0, v1 = *(unsigned short*)&l1;
    unsigned short v2 = *(unsigned short*)&l2, v3 = *(unsigned short*)&l3;
    hi4.x = (uint32_t)u0 | ((uint32_t)u1 << 16);
    hi4.y = (uint32_t)u2 | ((uint32_t)u3 << 16);
    lo4.x = (uint32_t)v0 | ((uint32_t)v1 << 16);
    lo4.y = (uint32_t)v2 | ((uint32_t)v3 << 16);
}

// split two floats, pack hi pair and lo pair as bf16x2
__device__ __forceinline__ void split2pack(float x, float y,
                                           uint32_t& hp, uint32_t& lp)
{
    __nv_bfloat16 hx = __float2bfloat16(x), hy = __float2bfloat16(y);
    __nv_bfloat16 lx = __float2bfloat16(x - __bfloat162float(hx));
    __nv_bfloat16 ly = __float2bfloat16(y - __bfloat162float(hy));
    unsigned short a = *(unsigned short*)&hx, b = *(unsigned short*)&hy;
    unsigned short c = *(unsigned short*)&lx, d = *(unsigned short*)&ly;
    hp = (uint32_t)a | ((uint32_t)b << 16);
    lp = (uint32_t)c | ((uint32_t)d << 16);
}

// ---------------------------------------------------------------------------
// fp32 -> (hi, lo) bf16 split, elementwise.
// ---------------------------------------------------------------------------
__global__ void split_kernel(const float4* __restrict__ src,
                             uint2* __restrict__ hi, uint2* __restrict__ lo,
                             int n4)
{
    int i = blockIdx.x * blockDim.x + threadIdx.x;
    if (i < n4) {
        uint2 h4, l4;
        split4(src[i], h4, l4);
        hi[i] = h4;
        lo[i] = l4;
    }
}

// ---------------------------------------------------------------------------
// bf16-split tensor-core GEMM, cp.async 4-stage pipeline (proven, R10).
// ---------------------------------------------------------------------------
#define SK 40
#define ARR_B (128*SK*2)
#define STG_B (4*ARR_B)
#define NSTG 4
#define GBF_SMEM (NSTG*STG_B)

__global__ __launch_bounds__(256) void gemm_bf(
    const uint16_t* __restrict__ Ah, const uint16_t* __restrict__ Al,
    const uint16_t* __restrict__ Wh, const uint16_t* __restrict__ Wl,
    float* __restrict__ Cout, const float* __restrict__ mixsrc,
    const float* __restrict__ lambp, int domix)
{
    extern __shared__ __align__(16) char dsm[];
    const uint32_t sbase = smem_u32(dsm);
    const int tid  = threadIdx.x;
    const int wid  = tid >> 5;
    const int lane = tid & 31;
    const int warp_r = wid & 3;
    const int warp_c = wid >> 2;
    const int row0 = blockIdx.x * 128;
    const int col0 = blockIdx.y * 128;

    float d[2][8][4];
    #pragma unroll
    for (int mt = 0; mt < 2; mt++)
        #pragma unroll
        for (int nt = 0; nt < 8; nt++)
            #pragma unroll
            for (int e = 0; e < 4; e++) d[mt][nt][e] = 0.f;

    const uint32_t a_elem = (uint32_t)((warp_r*32 + (lane & 15)) * SK + (lane >> 4) * 8);
    const uint32_t b_elem = (uint32_t)((warp_c*64 + (lane & 7) + ((lane >> 4) & 1) * 8) * SK
                                       + ((lane >> 3) & 1) * 8);

    const int cr0 = tid >> 2;
    const int cc0 = tid & 3;
    #define ISSUE_STAGE(st, kb)                                                   \
    do {                                                                          \
        uint32_t sb_ = sbase + (uint32_t)(st) * STG_B;                            \
        int koff_ = (kb) * 32;                                                    \
        { int r_ = cr0;                                                           \
          uint32_t doff_ = (uint32_t)(r_ * 80 + cc0 * 16);                        \
          size_t ga_ = (size_t)(row0 + r_) * Cc + koff_ + cc0 * 8;                \
          size_t gw_ = (size_t)(col0 + r_) * Cc + koff_ + cc0 * 8;                \
          cp16(sb_ + doff_,             Ah + ga_);                                \
          cp16(sb_ + ARR_B + doff_,     Al + ga_);                                \
          cp16(sb_ + 2*ARR_B + doff_,   Wh + gw_);                                \
          cp16(sb_ + 3*ARR_B + doff_,   Wl + gw_); }                              \
        { int r_ = cr0 + 64;                                                      \
          uint32_t doff_ = (uint32_t)(r_ * 80 + cc0 * 16);                        \
          size_t ga_ = (size_t)(row0 + r_) * Cc + koff_ + cc0 * 8;                \
          size_t gw_ = (size_t)(col0 + r_) * Cc + koff_ + cc0 * 8;                \
          cp16(sb_ + doff_,             Ah + ga_);                                \
          cp16(sb_ + ARR_B + doff_,     Al + ga_);                                \
          cp16(sb_ + 2*ARR_B + doff_,   Wh + gw_);                                \
          cp16(sb_ + 3*ARR_B + doff_,   Wl + gw_); }                              \
    } while (0)

    ISSUE_STAGE(0, 0); CP_COMMIT();
    ISSUE_STAGE(1, 1); CP_COMMIT();
    ISSUE_STAGE(2, 2); CP_COMMIT();

    for (int kb = 0; kb < 32; kb++) {
        CP_WAIT2();
        __syncthreads();

        if (kb + 3 < 32) {
            ISSUE_STAGE((kb + 3) & 3, kb + 3);
        }
        CP_COMMIT();

        const uint32_t sb = sbase + (uint32_t)(kb & 3) * STG_B;
        const uint32_t ah_b = sb;
        const uint32_t al_b = sb + ARR_B;
        const uint32_t wh_b = sb + 2*ARR_B;
        const uint32_t wl_b = sb + 3*ARR_B;

        #pragma unroll
        for (int ks = 0; ks < 2; ks++) {
            uint32_t ah[2][4], al[2][4];
            #pragma unroll
            for (int mt = 0; mt < 2; mt++) {
                uint32_t off = 2u * (a_elem + (uint32_t)mt * 16 * SK + (uint32_t)ks * 16);
                ldm4(ah[mt], ah_b + off);
                ldm4(al[mt], al_b + off);
            }
            uint32_t bh[4][4], bl[4][4];
            #pragma unroll
            for (int g = 0; g < 4; g++) {
                uint32_t off = 2u * (b_elem + (uint32_t)g * 16 * SK + (uint32_t)ks * 16);
                ldm4(bh[g], wh_b + off);
                ldm4(bl[g], wl_b + off);
            }
            #pragma unroll
            for (int mt = 0; mt < 2; mt++) {
                #pragma unroll
                for (int g = 0; g < 4; g++) {
                    mma16816(d[mt][2*g],   ah[mt], bh[g][0], bh[g][1]);
                    mma16816(d[mt][2*g+1], ah[mt], bh[g][2], bh[g][3]);
                    mma16816(d[mt][2*g],   ah[mt], bl[g][0], bl[g][1]);
                    mma16816(d[mt][2*g+1], ah[mt], bl[g][2], bl[g][3]);
                    mma16816(d[mt][2*g],   al[mt], bh[g][0], bh[g][1]);
                    mma16816(d[mt][2*g+1], al[mt], bh[g][2], bh[g][3]);
                }
            }
        }
        __syncthreads();
    }
    #undef ISSUE_STAGE

    const float lam = domix ? *lambp : 0.f;
    const int rbase = row0 + warp_r * 32 + (lane >> 2);
    const int cbase = col0 + warp_c * 64 + (lane & 3) * 2;
    #pragma unroll
    for (int mt = 0; mt < 2; mt++) {
        #pragma unroll
        for (int nt = 0; nt < 8; nt++) {
            int rr = rbase + mt * 16;
            int cc = cbase + nt * 8;
            float2 lo = make_float2(d[mt][nt][0], d[mt][nt][1]);
            float2 hi = make_float2(d[mt][nt][2], d[mt][nt][3]);
            if (domix) {
                float2 m0 = *(const float2*)(mixsrc + (size_t)rr * Cc + cc);
                float2 m1 = *(const float2*)(mixsrc + (size_t)(rr + 8) * Cc + cc);
                lo.x = (1.f - lam) * lo.x + lam * m0.x;
                lo.y = (1.f - lam) * lo.y + lam * m0.y;
                hi.x = (1.f - lam) * hi.x + lam * m1.x;
                hi.y = (1.f - lam) * hi.y + lam * m1.y;
            }
            *(float2*)(Cout + (size_t)rr * Cc + cc) = lo;
            *(float2*)(Cout + (size_t)(rr + 8) * Cc + cc) = hi;
        }
    }
}

// ---------------------------------------------------------------------------
// RoPE tables (fp64 trig; immune to --use_fast_math substitution).
// ---------------------------------------------------------------------------
__global__ void rope_table_kernel(float* __restrict__ ctab,
                                  float* __restrict__ stab)
{
    int t    = blockIdx.x;
    int lane = threadIdx.x;
    float invf = (float)exp2(-(double)lane * (13.287712379549449 / 32.0));
    float fr   = __fmul_rn((float)t, invf);
    ctab[t * 32 + lane] = (float)cos((double)fr);
    stab[t * 32 + lane] = (float)sin((double)fr);
}

// ---------------------------------------------------------------------------
// RMSNorm + RoPE, reading fp32 q/k and writing hi/lo bf16 splits.
// q additionally pre-scaled by 1/sqrt(D)=0.125 (folded into the split).
// ---------------------------------------------------------------------------
__global__ __launch_bounds__(256) void rmsrope_split(
    const float* __restrict__ qsrc, const float* __restrict__ ksrc,
    uint16_t* __restrict__ qh, uint16_t* __restrict__ ql,
    uint16_t* __restrict__ kh, uint16_t* __restrict__ kl,
    const float* __restrict__ ctab, const float* __restrict__ stab)
{
    const int isk = blockIdx.y;
    const float* src = isk ? ksrc : qsrc;
    uint16_t* dh = isk ? kh : qh;
    uint16_t* dl = isk ? kl : ql;
    const float scale = isk ? 1.0f : 0.125f;

    const int warp = threadIdx.x >> 5;
    const int lane = threadIdx.x & 31;
    const int row  = blockIdx.x * 8 + warp;
    const int t    = (row / Hh) % Tt;

    const float* base = src + (size_t)row * 64;
    float x1 = base[lane];
    float x2 = base[lane + 32];

    float ss = x1 * x1 + x2 * x2;
    #pragma unroll
    for (int off = 16; off; off >>= 1)
        ss += __shfl_xor_sync(0xffffffffu, ss, off);

    float r = rsqrtf(ss * (1.0f / 64.0f) + 1.1920929e-7f);
    float c = __ldg(&ctab[t * 32 + lane]);
    float s = __ldg(&stab[t * 32 + lane]);

    float n1 = x1 * r, n2 = x2 * r;
    float y1 = (n1 * c + n2 * s) * scale;
    float y2 = (n2 * c - n1 * s) * scale;

    size_t o = (size_t)row * 64;
    __nv_bfloat16 h1 = __float2bfloat16(y1);
    __nv_bfloat16 h2 = __float2bfloat16(y2);
    __nv_bfloat16 l1 = __float2bfloat16(y1 - __bfloat162float(h1));
    __nv_bfloat16 l2 = __float2bfloat16(y2 - __bfloat162float(h2));
    dh[o + lane]      = *(unsigned short*)&h1;
    dh[o + lane + 32] = *(unsigned short*)&h2;
    dl[o + lane]      = *(unsigned short*)&l1;
    dl[o + lane + 32] = *(unsigned short*)&l2;
}

// ---------------------------------------------------------------------------
// Flash attention on mma.sync (bf16 hi/lo split), causal, online softmax.
// CTA: 128 queries x one (b,h). 8 warps x 16 q-rows. Key tiles of 64,
// cp.async double-buffered. Output written as hi/lo bf16 into oh/ol.
// ---------------------------------------------------------------------------
#define FSK 72
#define FROWB (FSK*2)          /* 144 bytes per smem row */
#define F_QL 18432
#define F_STG 36864
#define F_STGB 36864           /* Kh,Kl,Vh,Vl @ 9216 each */
#define FLASH_SMEM (F_STG + 2*F_STGB)   /* 110592 */

__global__ __launch_bounds__(256, 1) void flash_mma(
    const uint16_t* __restrict__ qh, const uint16_t* __restrict__ ql,
    const uint16_t* __restrict__ kh, const uint16_t* __restrict__ kl,
    const uint16_t* __restrict__ vh, const uint16_t* __restrict__ vl,
    uint16_t* __restrict__ oh, uint16_t* __restrict__ ol)
{
    extern __shared__ __align__(16) char fsm[];
    const uint32_t sb = smem_u32(fsm);
    const int tid = threadIdx.x;
    const int wid = tid >> 5;
    const int lane = tid & 31;
    const int qblk = gridDim.x - 1 - blockIdx.x;     // heavy first
    const int bh = blockIdx.y;
    const int b = bh >> 4, h = bh & 15;
    const int q0 = qblk * 128;
    const int nkt = 2 * qblk + 2;
    const size_t rowbase = (size_t)b * Tt * Cc + (size_t)h * Dd;

    // stage loader: K/V hi+lo, 64 rows x 128B each
    #define F_ISSUE(st, kt)                                                     \
    do {                                                                        \
        uint32_t s_ = sb + F_STG + (uint32_t)(st) * F_STGB;                     \
        int k0_ = (kt) * 64;                                                    \
        _Pragma("unroll")                                                       \
        for (int i_ = 0; i_ < 2; i_++) {                                        \
            int c_ = tid + 256 * i_;                                            \
            int r_ = c_ >> 3, cq_ = c_ & 7;                                     \
            size_t g_ = rowbase + (size_t)(k0_ + r_) * Cc + cq_ * 8;            \
            uint32_t d_ = s_ + (uint32_t)(r_ * FROWB + cq_ * 16);               \
            cp16(d_,         kh + g_);                                          \
            cp16(d_ +  9216, kl + g_);                                          \
            cp16(d_ + 18432, vh + g_);                                          \
            cp16(d_ + 27648, vl + g_);                                          \
        }                                                                       \
    } while (0)

    // Prologue: Q (128 rows x 128B, hi+lo) + stage 0 in one group
    #pragma unroll
    for (int i = 0; i < 4; i++) {
        int c = tid + 256 * i;
        int r = c >> 3, cq = c & 7;
        size_t g = rowbase + (size_t)(q0 + r) * Cc + cq * 8;
        uint32_t d = sb + (uint32_t)(r * FROWB + cq * 16);
        cp16(d, qh + g);
        cp16(d + F_QL, ql + g);
    }
    F_ISSUE(0, 0);
    CP_COMMIT();

    // fragment addressing
    const uint32_t a_off = (uint32_t)((16*wid + (lane & 15)) * FROWB + (lane >> 4) * 16);
    const uint32_t bk_off = (uint32_t)(((lane & 7) + ((lane >> 4) & 1) * 8) * FROWB
                                       + ((lane >> 3) & 1) * 16);
    const uint32_t bv_off = (uint32_t)(((lane & 7) + ((lane >> 3) & 1) * 8) * FROWB
                                       + ((lane >> 4) & 1) * 16);

    uint32_t qfh[4][4], qfl[4][4];
    float o[8][4];
    #pragma unroll
    for (int j = 0; j < 8; j++)
        #pragma unroll
        for (int e = 0; e < 4; e++) o[j][e] = 0.f;
    float mrow[2] = {-1e30f, -1e30f};
    float lrow[2] = {0.f, 0.f};

    for (int kt = 0; kt < nkt; kt++) {
        if (kt + 1 < nkt) {
            F_ISSUE((kt + 1) & 1, kt + 1);
            CP_COMMIT();
            CP_WAIT1();
        } else {
            CP_WAIT0();
        }
        __syncthreads();

        if (kt == 0) {
            #pragma unroll
            for (int ks = 0; ks < 4; ks++) {
                ldm4(qfh[ks], sb + a_off + ks * 32);
                ldm4(qfl[ks], sb + F_QL + a_off + ks * 32);
            }
        }

        const uint32_t stg = sb + F_STG + (uint32_t)(kt & 1) * F_STGB;

        // S = Qh*Kh + Qh*Kl + Ql*Kh
        float s[8][4];
        #pragma unroll
        for (int j = 0; j < 8; j++)
            #pragma unroll
            for (int e = 0; e < 4; e++) s[j][e] = 0.f;

        #pragma unroll
        for (int ks = 0; ks < 4; ks++) {
            #pragma unroll
            for (int g = 0; g < 4; g++) {
                uint32_t khf[4], klf[4];
                uint32_t off = bk_off + (uint32_t)g * 16 * FROWB + (uint32_t)ks * 32;
                ldm4(khf, stg + off);
                ldm4(klf, stg + 9216 + off);
                mma16816(s[2*g],   qfh[ks], khf[0], khf[1]);
                mma16816(s[2*g+1], qfh[ks], khf[2], khf[3]);
                mma16816(s[2*g],   qfh[ks], klf[0], klf[1]);
                mma16816(s[2*g+1], qfh[ks], klf[2], klf[3]);
                mma16816(s[2*g],   qfl[ks], khf[0], khf[1]);
                mma16816(s[2*g+1], qfl[ks], khf[2], khf[3]);
            }
        }

        // causal mask (only the last two key tiles can cross the diagonal)
        if (kt >= 2 * qblk) {
            int qg0 = q0 + 16 * wid + (lane >> 2);
            int kgb = kt * 64 + (lane & 3) * 2;
            #pragma unroll
            for (int j = 0; j < 8; j++) {
                int kg = kgb + j * 8;
                if (kg     > qg0)     s[j][0] = -1e30f;
                if (kg + 1 > qg0)     s[j][1] = -1e30f;
                if (kg     > qg0 + 8) s[j][2] = -1e30f;
                if (kg + 1 > qg0 + 8) s[j][3] = -1e30f;
            }
        }

        // online softmax (rows r = lane>>2 and r+8)
        float tm0 = -1e30f, tm1 = -1e30f;
        #pragma unroll
        for (int j = 0; j < 8; j++) {
            tm0 = fmaxf(tm0, fmaxf(s[j][0], s[j][1]));
            tm1 = fmaxf(tm1, fmaxf(s[j][2], s[j][3]));
        }
        tm0 = fmaxf(tm0, __shfl_xor_sync(0xffffffffu, tm0, 1));
        tm0 = fmaxf(tm0, __shfl_xor_sync(0xffffffffu, tm0, 2));
        tm1 = fmaxf(tm1, __shfl_xor_sync(0xffffffffu, tm1, 1));
        tm1 = fmaxf(tm1, __shfl_xor_sync(0xffffffffu, tm1, 2));
        float mn0 = fmaxf(mrow[0], tm0);
        float mn1 = fmaxf(mrow[1], tm1);
        float al0 = __expf(mrow[0] - mn0);
        float al1 = __expf(mrow[1] - mn1);
        float rs0 = 0.f, rs1 = 0.f;
        #pragma unroll
        for (int j = 0; j < 8; j++) {
            s[j][0] = __expf(s[j][0] - mn0);
            s[j][1] = __expf(s[j][1] - mn0);
            s[j][2] = __expf(s[j][2] - mn1);
            s[j][3] = __expf(s[j][3] - mn1);
            rs0 += s[j][0] + s[j][1];
            rs1 += s[j][2] + s[j][3];
        }
        rs0 += __shfl_xor_sync(0xffffffffu, rs0, 1);
        rs0 += __shfl_xor_sync(0xffffffffu, rs0, 2);
        rs1 += __shfl_xor_sync(0xffffffffu, rs1, 1);
        rs1 += __shfl_xor_sync(0xffffffffu, rs1, 2);
        lrow[0] = lrow[0] * al0 + rs0;
        lrow[1] = lrow[1] * al1 + rs1;
        mrow[0] = mn0;
        mrow[1] = mn1;
        #pragma unroll
        for (int j = 0; j < 8; j++) {
            o[j][0] *= al0; o[j][1] *= al0;
            o[j][2] *= al1; o[j][3] *= al1;
        }

        // P fragments (hi/lo), reusing the S accumulator layout as A layout
        uint32_t pfh[4][4], pfl[4][4];
        #pragma unroll
        for (int ks = 0; ks < 4; ks++) {
            split2pack(s[2*ks][0],   s[2*ks][1],   pfh[ks][0], pfl[ks][0]);
            split2pack(s[2*ks][2],   s[2*ks][3],   pfh[ks][1], pfl[ks][1]);
            split2pack(s[2*ks+1][0], s[2*ks+1][1], pfh[ks][2], pfl[ks][2]);
            split2pack(s[2*ks+1][2], s[2*ks+1][3], pfh[ks][3], pfl[ks][3]);
        }

        // O += Ph*Vh + Ph*Vl + Pl*Vh  (V via ldmatrix.trans from [key][dim])
        #pragma unroll
        for (int ks = 0; ks < 4; ks++) {
            #pragma unroll
            for (int g = 0; g < 4; g++) {
                uint32_t vhf[4], vlf[4];
                uint32_t off = bv_off + (uint32_t)ks * 16 * FROWB + (uint32_t)g * 32;
                ldm4t(vhf, stg + 18432 + off);
                ldm4t(vlf, stg + 27648 + off);
                mma16816(o[2*g],   pfh[ks], vhf[0], vhf[1]);
                mma16816(o[2*g+1], pfh[ks], vhf[2], vhf[3]);
                mma16816(o[2*g],   pfh[ks], vlf[0], vlf[1]);
                mma16816(o[2*g+1], pfh[ks], vlf[2], vlf[3]);
                mma16816(o[2*g],   pfl[ks], vhf[0], vhf[1]);
                mma16816(o[2*g+1], pfl[ks], vhf[2], vhf[3]);
            }
        }
        __syncthreads();
    }
    #undef F_ISSUE

    // Epilogue: divide by lsum, split to bf16 hi/lo, store.
    float inv0 = 1.0f / lrow[0];
    float inv1 = 1.0f / lrow[1];
    int t0 = q0 + 16 * wid + (lane >> 2);
    int t1 = t0 + 8;
    #pragma unroll
    for (int j = 0; j < 8; j++) {
        int cb = j * 8 + (lane & 3) * 2;
        size_t e0 = rowbase + (size_t)t0 * Cc + cb;
        size_t e1 = rowbase + (size_t)t1 * Cc + cb;
        uint32_t hp, lp;
        split2pack(o[j][0] * inv0, o[j][1] * inv0, hp, lp);
        *(uint32_t*)(oh + e0) = hp;
        *(uint32_t*)(ol + e0) = lp;
        split2pack(o[j][2] * inv1, o[j][3] * inv1, hp, lp);
        *(uint32_t*)(oh + e1) = hp;
        *(uint32_t*)(ol + e1) = lp;
    }
}

// ---------------------------------------------------------------------------
__global__ void copy_kernel(const float4* __restrict__ src,
                            float4* __restrict__ dst, int n4)
{
    for (int i = blockIdx.x * blockDim.x + threadIdx.x; i < n4;
         i += gridDim.x * blockDim.x)
        dst[i] = src[i];
}

// ---------------------------------------------------------------------------
extern "C" void kernel_launch(void* const* d_in, const int* in_sizes, int n_in,
                              void* d_out, int out_size)
{
    const float *x, *v1, *Wq, *Wk, *Wv, *Wp, *lamb;
    if (in_sizes[0] == Mm * Cc) {            // dict order
        x    = (const float*)d_in[0];
        v1   = (const float*)d_in[1];
        Wq   = (const float*)d_in[2];
        Wk   = (const float*)d_in[3];
        Wv   = (const float*)d_in[4];
        Wp   = (const float*)d_in[5];
        lamb = (const float*)d_in[6];
    } else {                                  // alphabetical order
        Wk   = (const float*)d_in[0];
        Wp   = (const float*)d_in[1];
        Wq   = (const float*)d_in[2];
        Wv   = (const float*)d_in[3];
        lamb = (const float*)d_in[4];
        v1   = (const float*)d_in[5];
        x    = (const float*)d_in[6];
    }
    float* out = (float*)d_out;

    float *q, *k, *v, *ctab, *stab;
    uint16_t *xh, *xl, *wh, *wl, *qhp, *qlp, *khp, *klp, *vhp, *vlp;
    cudaGetSymbolAddress((void**)&q,    g_q);
    cudaGetSymbolAddress((void**)&k,    g_k);
    cudaGetSymbolAddress((void**)&v,    g_v);
    cudaGetSymbolAddress((void**)&ctab, g_cos);
    cudaGetSymbolAddress((void**)&stab, g_sin);
    cudaGetSymbolAddress((void**)&xh,   g_xh);
    cudaGetSymbolAddress((void**)&xl,   g_xl);
    cudaGetSymbolAddress((void**)&wh,   g_wh);
    cudaGetSymbolAddress((void**)&wl,   g_wl);
    cudaGetSymbolAddress((void**)&qhp,  g_qh);
    cudaGetSymbolAddress((void**)&qlp,  g_ql);
    cudaGetSymbolAddress((void**)&khp,  g_kh);
    cudaGetSymbolAddress((void**)&klp,  g_kl);
    cudaGetSymbolAddress((void**)&vhp,  g_vh);
    cudaGetSymbolAddress((void**)&vlp,  g_vl);

    rope_table_kernel<<<Tt, 32>>>(ctab, stab);

    const int nx4 = Mm * Cc / 4;
    const int nw4 = Cc * Cc / 4;
    split_kernel<<<(nx4 + 255) / 256, 256>>>((const float4*)x,
        (uint2*)xh, (uint2*)xl, nx4);
    split_kernel<<<(nw4 + 255) / 256, 256>>>((const float4*)Wq,
        (uint2*)(wh + 0ll*Cc*Cc), (uint2*)(wl + 0ll*Cc*Cc), nw4);
    split_kernel<<<(nw4 + 255) / 256, 256>>>((const float4*)Wk,
        (uint2*)(wh + 1ll*Cc*Cc), (uint2*)(wl + 1ll*Cc*Cc), nw4);
    split_kernel<<<(nw4 + 255) / 256, 256>>>((const float4*)Wv,
        (uint2*)(wh + 2ll*Cc*Cc), (uint2*)(wl + 2ll*Cc*Cc), nw4);
    split_kernel<<<(nw4 + 255) / 256, 256>>>((const float4*)Wp,
        (uint2*)(wh + 3ll*Cc*Cc), (uint2*)(wl + 3ll*Cc*Cc), nw4);

    cudaFuncSetAttribute(gemm_bf,
                         cudaFuncAttributeMaxDynamicSharedMemorySize, GBF_SMEM);
    dim3 ggrid(Mm / 128, Cc / 128);
    gemm_bf<<<ggrid, 256, GBF_SMEM>>>(xh, xl, wh + 0ll*Cc*Cc, wl + 0ll*Cc*Cc,
                                      q, (const float*)0, (const float*)0, 0);
    gemm_bf<<<ggrid, 256, GBF_SMEM>>>(xh, xl, wh + 1ll*Cc*Cc, wl + 1ll*Cc*Cc,
                                      k, (const float*)0, (const float*)0, 0);
    gemm_bf<<<ggrid, 256, GBF_SMEM>>>(xh, xl, wh + 2ll*Cc*Cc, wl + 2ll*Cc*Cc,
                                      v, v1, lamb, 1);

    rmsrope_split<<<dim3(Bb * Tt * Hh / 8, 2), 256>>>(q, k, qhp, qlp, khp, klp,
                                                      ctab, stab);
    split_kernel<<<(nx4 + 255) / 256, 256>>>((const float4*)v,
        (uint2*)vhp, (uint2*)vlp, nx4);

    cudaFuncSetAttribute(flash_mma,
                         cudaFuncAttributeMaxDynamicSharedMemorySize, FLASH_SMEM);
    flash_mma<<<dim3(Tt / 128, Bb * Hh), 256, FLASH_SMEM>>>(
        qhp, qlp, khp, klp, vhp, vlp, xh, xl);

    gemm_bf<<<ggrid, 256, GBF_SMEM>>>(xh, xl, wh + 3ll*Cc*Cc, wl + 3ll*Cc*Cc,
                                      out, (const float*)0, (const float*)0, 0);

    if (out_size >= 2 * Mm * Cc)
        copy_kernel<<<2048, 256>>>((const float4*)v1,
                                   (float4*)(out + (size_t)Mm * Cc),
                                   (Mm * Cc) / 4);
}

// round 13
// speedup vs baseline: 3.4385x; 1.0510x over previous
#include <cuda_runtime.h>
#include <cuda_bf16.h>
#include <cstdint>
#include <math.h>

#define Bb 4
#define Tt 2048
#define Cc 1024
#define Hh 16
#define Dd 64
#define Mm (Bb*Tt)   /* 8192 rows */

// Scratch (device globals: allocation-free rule)
__device__ float g_q[Mm*Cc];
__device__ float g_k[Mm*Cc];
__device__ float g_cos[Tt*32];
__device__ float g_sin[Tt*32];
// bf16 hi/lo split operands
__device__ uint16_t g_xh[Mm*Cc];   // x split; later reused for attention output
__device__ uint16_t g_xl[Mm*Cc];
__device__ uint16_t g_wh[4*Cc*Cc];
__device__ uint16_t g_wl[4*Cc*Cc];
__device__ uint16_t g_qh[Mm*Cc];
__device__ uint16_t g_ql[Mm*Cc];
__device__ uint16_t g_kh[Mm*Cc];
__device__ uint16_t g_kl[Mm*Cc];
__device__ uint16_t g_vh[Mm*Cc];
__device__ uint16_t g_vl[Mm*Cc];

// ========================== helpers ===========================
__device__ __forceinline__ uint32_t smem_u32(const void* p)
{
    uint32_t a;
    asm("{ .reg .u64 t; cvta.to.shared.u64 t, %1; cvt.u32.u64 %0, t; }"
        : "=r"(a) : "l"(p));
    return a;
}

__device__ __forceinline__ void ldm4(uint32_t* r, uint32_t addr)
{
    asm volatile("ldmatrix.sync.aligned.m8n8.x4.shared.b16 {%0,%1,%2,%3}, [%4];"
                 : "=r"(r[0]), "=r"(r[1]), "=r"(r[2]), "=r"(r[3])
                 : "r"(addr));
}

__device__ __forceinline__ void ldm4t(uint32_t* r, uint32_t addr)
{
    asm volatile("ldmatrix.sync.aligned.m8n8.x4.trans.shared.b16 {%0,%1,%2,%3}, [%4];"
                 : "=r"(r[0]), "=r"(r[1]), "=r"(r[2]), "=r"(r[3])
                 : "r"(addr));
}

__device__ __forceinline__ void mma16816(float* d, const uint32_t* a,
                                         uint32_t b0, uint32_t b1)
{
    asm volatile(
        "mma.sync.aligned.m16n8k16.row.col.f32.bf16.bf16.f32 "
        "{%0,%1,%2,%3}, {%4,%5,%6,%7}, {%8,%9}, {%0,%1,%2,%3};"
        : "+f"(d[0]), "+f"(d[1]), "+f"(d[2]), "+f"(d[3])
        : "r"(a[0]), "r"(a[1]), "r"(a[2]), "r"(a[3]), "r"(b0), "r"(b1));
}

__device__ __forceinline__ void cp16(uint32_t dst, const void* src)
{
    asm volatile("cp.async.cg.shared.global [%0], [%1], 16;"
                 :: "r"(dst), "l"(src));
}
#define CP_COMMIT() asm volatile("cp.async.commit_group;" ::: "memory")
#define CP_WAIT2()  asm volatile("cp.async.wait_group 2;"  ::: "memory")
#define CP_WAIT1()  asm volatile("cp.async.wait_group 1;"  ::: "memory")
#define CP_WAIT0()  asm volatile("cp.async.wait_group 0;"  ::: "memory")

__device__ __forceinline__ void split4(float4 a, uint2& hi4, uint2& lo4)
{
    __nv_bfloat16 h0 = __float2bfloat16(a.x), h1 = __float2bfloat16(a.y);
    __nv_bfloat16 h2 = __float2bfloat16(a.z), h3 = __float2bfloat16(a.w);
    __nv_bfloat16 l0 = __float2bfloat16(a.x - __bfloat162float(h0));
    __nv_bfloat16 l1 = __float2bfloat16(a.y - __bfloat162float(h1));
    __nv_bfloat16 l2 = __float2bfloat16(a.z - __bfloat162float(h2));
    __nv_bfloat16 l3 = __float2bfloat16(a.w - __bfloat162float(h3));
    unsigned short u0 = *(unsigned short*)&h0, u1 = *(unsigned short*)&h1;
    unsigned short u2 = *(unsigned short*)&h2, u3 = *(unsigned short*)&h3;
    unsigned short v0 = *(unsigned short*)&l0, v1 = *(unsigned short*)&l1;
    unsigned short v2 = *(unsigned short*)&l2, v3 = *(unsigned short*)&l3;
    hi4.x = (uint32_t)u0 | ((uint32_t)u1 << 16);
    hi4.y = (uint32_t)u2 | ((uint32_t)u3 << 16);
    lo4.x = (uint32_t)v0 | ((uint32_t)v1 << 16);
    lo4.y = (uint32_t)v2 | ((uint32_t)v3 << 16);
}

__device__ __forceinline__ void split2pack(float x, float y,
                                           uint32_t& hp, uint32_t& lp)
{
    __nv_bfloat16 hx = __float2bfloat16(x), hy = __float2bfloat16(y);
    __nv_bfloat16 lx = __float2bfloat16(x - __bfloat162float(hx));
    __nv_bfloat16 ly = __float2bfloat16(y - __bfloat162float(hy));
    unsigned short a = *(unsigned short*)&hx, b = *(unsigned short*)&hy;
    unsigned short c = *(unsigned short*)&lx, d = *(unsigned short*)&ly;
    hp = (uint32_t)a | ((uint32_t)b << 16);
    lp = (uint32_t)c | ((uint32_t)d << 16);
}

// ---------------------------------------------------------------------------
// fp32 -> (hi, lo) bf16 split, elementwise (x / att).
// ---------------------------------------------------------------------------
__global__ void split_kernel(const float4* __restrict__ src,
                             uint2* __restrict__ hi, uint2* __restrict__ lo,
                             int n4)
{
    int i = blockIdx.x * blockDim.x + threadIdx.x;
    if (i < n4) {
        uint2 h4, l4;
        split4(src[i], h4, l4);
        hi[i] = h4;
        lo[i] = l4;
    }
}

// All four weights in one launch.
__global__ void split_w_kernel(const float4* __restrict__ w0,
                               const float4* __restrict__ w1,
                               const float4* __restrict__ w2,
                               const float4* __restrict__ w3,
                               uint2* __restrict__ hi, uint2* __restrict__ lo,
                               int n4each)
{
    int i = blockIdx.x * blockDim.x + threadIdx.x;
    if (i < 4 * n4each) {
        int w = i / n4each;
        int j = i - w * n4each;
        const float4* src = (w == 0) ? w0 : (w == 1) ? w1 : (w == 2) ? w2 : w3;
        uint2 h4, l4;
        split4(src[j], h4, l4);
        hi[i] = h4;
        lo[i] = l4;
    }
}

// ---------------------------------------------------------------------------
// Shared GEMM mainloop (proven R10/R12): accumulates d[2][8][4] for a
// 128x128 tile of sum_k A[m][k]*W[n][k] with hi/lo split operands.
// ---------------------------------------------------------------------------
#define SK 40
#define ARR_B (128*SK*2)
#define STG_B (4*ARR_B)
#define NSTG 4
#define GBF_SMEM (NSTG*STG_B)

#define GEMM_MAINLOOP(Ah, Al, Wh, Wl, row0, col0)                                 \
    const uint32_t a_elem = (uint32_t)((warp_r*32 + (lane & 15)) * SK + (lane >> 4) * 8); \
    const uint32_t b_elem = (uint32_t)((warp_c*64 + (lane & 7) + ((lane >> 4) & 1) * 8) * SK \
                                       + ((lane >> 3) & 1) * 8);                  \
    const int cr0 = tid >> 2;                                                     \
    const int cc0 = tid & 3;                                                      \
    ISSUE_STAGE(0, 0); CP_COMMIT();                                               \
    ISSUE_STAGE(1, 1); CP_COMMIT();                                               \
    ISSUE_STAGE(2, 2); CP_COMMIT();                                               \
    for (int kb = 0; kb < 32; kb++) {                                             \
        CP_WAIT2();                                                               \
        __syncthreads();                                                          \
        if (kb + 3 < 32) {                                                        \
            ISSUE_STAGE((kb + 3) & 3, kb + 3);                                    \
        }                                                                         \
        CP_COMMIT();                                                              \
        const uint32_t sb = sbase + (uint32_t)(kb & 3) * STG_B;                   \
        const uint32_t ah_b = sb;                                                 \
        const uint32_t al_b = sb + ARR_B;                                         \
        const uint32_t wh_b = sb + 2*ARR_B;                                       \
        const uint32_t wl_b = sb + 3*ARR_B;                                       \
        _Pragma("unroll")                                                         \
        for (int ks = 0; ks < 2; ks++) {                                          \
            uint32_t ahf[2][4], alf[2][4];                                        \
            _Pragma("unroll")                                                     \
            for (int mt = 0; mt < 2; mt++) {                                      \
                uint32_t off = 2u * (a_elem + (uint32_t)mt * 16 * SK + (uint32_t)ks * 16); \
                ldm4(ahf[mt], ah_b + off);                                        \
                ldm4(alf[mt], al_b + off);                                        \
            }                                                                     \
            uint32_t bh[4][4], bl[4][4];                                          \
            _Pragma("unroll")                                                     \
            for (int g = 0; g < 4; g++) {                                         \
                uint32_t off = 2u * (b_elem + (uint32_t)g * 16 * SK + (uint32_t)ks * 16); \
                ldm4(bh[g], wh_b + off);                                          \
                ldm4(bl[g], wl_b + off);                                          \
            }                                                                     \
            _Pragma("unroll")                                                     \
            for (int mt = 0; mt < 2; mt++) {                                      \
                _Pragma("unroll")                                                 \
                for (int g = 0; g < 4; g++) {                                     \
                    mma16816(d[mt][2*g],   ahf[mt], bh[g][0], bh[g][1]);          \
                    mma16816(d[mt][2*g+1], ahf[mt], bh[g][2], bh[g][3]);          \
                    mma16816(d[mt][2*g],   ahf[mt], bl[g][0], bl[g][1]);          \
                    mma16816(d[mt][2*g+1], ahf[mt], bl[g][2], bl[g][3]);          \
                    mma16816(d[mt][2*g],   alf[mt], bh[g][0], bh[g][1]);          \
                    mma16816(d[mt][2*g+1], alf[mt], bh[g][2], bh[g][3]);          \
                }                                                                 \
            }                                                                     \
        }                                                                         \
        __syncthreads();                                                          \
    }

#define ISSUE_STAGE(st, kb)                                                       \
    do {                                                                          \
        uint32_t sb_ = sbase + (uint32_t)(st) * STG_B;                            \
        int koff_ = (kb) * 32;                                                    \
        { int r_ = cr0;                                                           \
          uint32_t doff_ = (uint32_t)(r_ * 80 + cc0 * 16);                        \
          size_t ga_ = (size_t)(row0 + r_) * Cc + koff_ + cc0 * 8;                \
          size_t gw_ = (size_t)(col0 + r_) * Cc + koff_ + cc0 * 8;                \
          cp16(sb_ + doff_,             Ah + ga_);                                \
          cp16(sb_ + ARR_B + doff_,     Al + ga_);                                \
          cp16(sb_ + 2*ARR_B + doff_,   Wh + gw_);                                \
          cp16(sb_ + 3*ARR_B + doff_,   Wl + gw_); }                              \
        { int r_ = cr0 + 64;                                                      \
          uint32_t doff_ = (uint32_t)(r_ * 80 + cc0 * 16);                        \
          size_t ga_ = (size_t)(row0 + r_) * Cc + koff_ + cc0 * 8;                \
          size_t gw_ = (size_t)(col0 + r_) * Cc + koff_ + cc0 * 8;                \
          cp16(sb_ + doff_,             Ah + ga_);                                \
          cp16(sb_ + ARR_B + doff_,     Al + ga_);                                \
          cp16(sb_ + 2*ARR_B + doff_,   Wh + gw_);                                \
          cp16(sb_ + 3*ARR_B + doff_,   Wl + gw_); }                              \
    } while (0)

// ---------------------------------------------------------------------------
// Fused QKV GEMM: gridDim.z selects {Wq->q fp32, Wk->k fp32, Wv->mix->vh/vl}.
// ---------------------------------------------------------------------------
__global__ __launch_bounds__(256) void gemm_qkv(
    const uint16_t* __restrict__ Ah, const uint16_t* __restrict__ Al,
    const uint16_t* __restrict__ WhB, const uint16_t* __restrict__ WlB,
    float* __restrict__ qout, float* __restrict__ kout,
    const float* __restrict__ v1, const float* __restrict__ lambp,
    uint16_t* __restrict__ vhout, uint16_t* __restrict__ vlout)
{
    extern __shared__ __align__(16) char dsm[];
    const uint32_t sbase = smem_u32(dsm);
    const int tid  = threadIdx.x;
    const int wid  = tid >> 5;
    const int lane = tid & 31;
    const int warp_r = wid & 3;
    const int warp_c = wid >> 2;
    const int row0 = blockIdx.x * 128;
    const int col0 = blockIdx.y * 128;
    const int z = blockIdx.z;
    const uint16_t* Wh = WhB + (size_t)z * Cc * Cc;
    const uint16_t* Wl = WlB + (size_t)z * Cc * Cc;

    float d[2][8][4];
    #pragma unroll
    for (int mt = 0; mt < 2; mt++)
        #pragma unroll
        for (int nt = 0; nt < 8; nt++)
            #pragma unroll
            for (int e = 0; e < 4; e++) d[mt][nt][e] = 0.f;

    GEMM_MAINLOOP(Ah, Al, Wh, Wl, row0, col0)

    const int rbase = row0 + warp_r * 32 + (lane >> 2);
    const int cbase = col0 + warp_c * 64 + (lane & 3) * 2;
    if (z < 2) {
        float* Cout = z ? kout : qout;
        #pragma unroll
        for (int mt = 0; mt < 2; mt++) {
            #pragma unroll
            for (int nt = 0; nt < 8; nt++) {
                int rr = rbase + mt * 16;
                int cc = cbase + nt * 8;
                *(float2*)(Cout + (size_t)rr * Cc + cc) =
                    make_float2(d[mt][nt][0], d[mt][nt][1]);
                *(float2*)(Cout + (size_t)(rr + 8) * Cc + cc) =
                    make_float2(d[mt][nt][2], d[mt][nt][3]);
            }
        }
    } else {
        const float lam = *lambp;
        #pragma unroll
        for (int mt = 0; mt < 2; mt++) {
            #pragma unroll
            for (int nt = 0; nt < 8; nt++) {
                int rr = rbase + mt * 16;
                int cc = cbase + nt * 8;
                size_t e0 = (size_t)rr * Cc + cc;
                size_t e1 = (size_t)(rr + 8) * Cc + cc;
                float2 m0 = *(const float2*)(v1 + e0);
                float2 m1 = *(const float2*)(v1 + e1);
                float a0 = (1.f - lam) * d[mt][nt][0] + lam * m0.x;
                float a1 = (1.f - lam) * d[mt][nt][1] + lam * m0.y;
                float a2 = (1.f - lam) * d[mt][nt][2] + lam * m1.x;
                float a3 = (1.f - lam) * d[mt][nt][3] + lam * m1.y;
                uint32_t hp, lp;
                split2pack(a0, a1, hp, lp);
                *(uint32_t*)(vhout + e0) = hp;
                *(uint32_t*)(vlout + e0) = lp;
                split2pack(a2, a3, hp, lp);
                *(uint32_t*)(vhout + e1) = hp;
                *(uint32_t*)(vlout + e1) = lp;
            }
        }
    }
}

// ---------------------------------------------------------------------------
// Proj GEMM (fp32 out, no mix) — same mainloop.
// ---------------------------------------------------------------------------
__global__ __launch_bounds__(256) void gemm_bf(
    const uint16_t* __restrict__ Ah, const uint16_t* __restrict__ Al,
    const uint16_t* __restrict__ Wh, const uint16_t* __restrict__ Wl,
    float* __restrict__ Cout)
{
    extern __shared__ __align__(16) char dsm[];
    const uint32_t sbase = smem_u32(dsm);
    const int tid  = threadIdx.x;
    const int wid  = tid >> 5;
    const int lane = tid & 31;
    const int warp_r = wid & 3;
    const int warp_c = wid >> 2;
    const int row0 = blockIdx.x * 128;
    const int col0 = blockIdx.y * 128;

    float d[2][8][4];
    #pragma unroll
    for (int mt = 0; mt < 2; mt++)
        #pragma unroll
        for (int nt = 0; nt < 8; nt++)
            #pragma unroll
            for (int e = 0; e < 4; e++) d[mt][nt][e] = 0.f;

    GEMM_MAINLOOP(Ah, Al, Wh, Wl, row0, col0)

    const int rbase = row0 + warp_r * 32 + (lane >> 2);
    const int cbase = col0 + warp_c * 64 + (lane & 3) * 2;
    #pragma unroll
    for (int mt = 0; mt < 2; mt++) {
        #pragma unroll
        for (int nt = 0; nt < 8; nt++) {
            int rr = rbase + mt * 16;
            int cc = cbase + nt * 8;
            *(float2*)(Cout + (size_t)rr * Cc + cc) =
                make_float2(d[mt][nt][0], d[mt][nt][1]);
            *(float2*)(Cout + (size_t)(rr + 8) * Cc + cc) =
                make_float2(d[mt][nt][2], d[mt][nt][3]);
        }
    }
}
#undef ISSUE_STAGE

// ---------------------------------------------------------------------------
// RoPE tables (fp64 trig; immune to --use_fast_math substitution).
// ---------------------------------------------------------------------------
__global__ void rope_table_kernel(float* __restrict__ ctab,
                                  float* __restrict__ stab)
{
    int t    = blockIdx.x;
    int lane = threadIdx.x;
    float invf = (float)exp2(-(double)lane * (13.287712379549449 / 32.0));
    float fr   = __fmul_rn((float)t, invf);
    ctab[t * 32 + lane] = (float)cos((double)fr);
    stab[t * 32 + lane] = (float)sin((double)fr);
}

// ---------------------------------------------------------------------------
// RMSNorm + RoPE, fp32 in -> hi/lo bf16 out (q pre-scaled by 0.125).
// ---------------------------------------------------------------------------
__global__ __launch_bounds__(256) void rmsrope_split(
    const float* __restrict__ qsrc, const float* __restrict__ ksrc,
    uint16_t* __restrict__ qh, uint16_t* __restrict__ ql,
    uint16_t* __restrict__ kh, uint16_t* __restrict__ kl,
    const float* __restrict__ ctab, const float* __restrict__ stab)
{
    const int isk = blockIdx.y;
    const float* src = isk ? ksrc : qsrc;
    uint16_t* dh = isk ? kh : qh;
    uint16_t* dl = isk ? kl : ql;
    const float scale = isk ? 1.0f : 0.125f;

    const int warp = threadIdx.x >> 5;
    const int lane = threadIdx.x & 31;
    const int row  = blockIdx.x * 8 + warp;
    const int t    = (row / Hh) % Tt;

    const float* base = src + (size_t)row * 64;
    float x1 = base[lane];
    float x2 = base[lane + 32];

    float ss = x1 * x1 + x2 * x2;
    #pragma unroll
    for (int off = 16; off; off >>= 1)
        ss += __shfl_xor_sync(0xffffffffu, ss, off);

    float r = rsqrtf(ss * (1.0f / 64.0f) + 1.1920929e-7f);
    float c = __ldg(&ctab[t * 32 + lane]);
    float s = __ldg(&stab[t * 32 + lane]);

    float n1 = x1 * r, n2 = x2 * r;
    float y1 = (n1 * c + n2 * s) * scale;
    float y2 = (n2 * c - n1 * s) * scale;

    size_t o = (size_t)row * 64;
    __nv_bfloat16 h1 = __float2bfloat16(y1);
    __nv_bfloat16 h2 = __float2bfloat16(y2);
    __nv_bfloat16 l1 = __float2bfloat16(y1 - __bfloat162float(h1));
    __nv_bfloat16 l2 = __float2bfloat16(y2 - __bfloat162float(h2));
    dh[o + lane]      = *(unsigned short*)&h1;
    dh[o + lane + 32] = *(unsigned short*)&h2;
    dl[o + lane]      = *(unsigned short*)&l1;
    dl[o + lane + 32] = *(unsigned short*)&l2;
}

// ---------------------------------------------------------------------------
// Flash attention on mma.sync (bf16 hi/lo split), causal (proven, R12).
// ---------------------------------------------------------------------------
#define FSK 72
#define FROWB (FSK*2)
#define F_QL 18432
#define F_STG 36864
#define F_STGB 36864
#define FLASH_SMEM (F_STG + 2*F_STGB)

__global__ __launch_bounds__(256, 1) void flash_mma(
    const uint16_t* __restrict__ qh, const uint16_t* __restrict__ ql,
    const uint16_t* __restrict__ kh, const uint16_t* __restrict__ kl,
    const uint16_t* __restrict__ vh, const uint16_t* __restrict__ vl,
    uint16_t* __restrict__ oh, uint16_t* __restrict__ ol)
{
    extern __shared__ __align__(16) char fsm[];
    const uint32_t sb = smem_u32(fsm);
    const int tid = threadIdx.x;
    const int wid = tid >> 5;
    const int lane = tid & 31;
    const int qblk = gridDim.x - 1 - blockIdx.x;
    const int bh = blockIdx.y;
    const int b = bh >> 4, h = bh & 15;
    const int q0 = qblk * 128;
    const int nkt = 2 * qblk + 2;
    const size_t rowbase = (size_t)b * Tt * Cc + (size_t)h * Dd;

    #define F_ISSUE(st, kt)                                                     \
    do {                                                                        \
        uint32_t s_ = sb + F_STG + (uint32_t)(st) * F_STGB;                     \
        int k0_ = (kt) * 64;                                                    \
        _Pragma("unroll")                                                       \
        for (int i_ = 0; i_ < 2; i_++) {                                        \
            int c_ = tid + 256 * i_;                                            \
            int r_ = c_ >> 3, cq_ = c_ & 7;                                     \
            size_t g_ = rowbase + (size_t)(k0_ + r_) * Cc + cq_ * 8;            \
            uint32_t d_ = s_ + (uint32_t)(r_ * FROWB + cq_ * 16);               \
            cp16(d_,         kh + g_);                                          \
            cp16(d_ +  9216, kl + g_);                                          \
            cp16(d_ + 18432, vh + g_);                                          \
            cp16(d_ + 27648, vl + g_);                                          \
        }                                                                       \
    } while (0)

    #pragma unroll
    for (int i = 0; i < 4; i++) {
        int c = tid + 256 * i;
        int r = c >> 3, cq = c & 7;
        size_t g = rowbase + (size_t)(q0 + r) * Cc + cq * 8;
        uint32_t d = sb + (uint32_t)(r * FROWB + cq * 16);
        cp16(d, qh + g);
        cp16(d + F_QL, ql + g);
    }
    F_ISSUE(0, 0);
    CP_COMMIT();

    const uint32_t a_off = (uint32_t)((16*wid + (lane & 15)) * FROWB + (lane >> 4) * 16);
    const uint32_t bk_off = (uint32_t)(((lane & 7) + ((lane >> 4) & 1) * 8) * FROWB
                                       + ((lane >> 3) & 1) * 16);
    const uint32_t bv_off = (uint32_t)(((lane & 7) + ((lane >> 3) & 1) * 8) * FROWB
                                       + ((lane >> 4) & 1) * 16);

    uint32_t qfh[4][4], qfl[4][4];
    float o[8][4];
    #pragma unroll
    for (int j = 0; j < 8; j++)
        #pragma unroll
        for (int e = 0; e < 4; e++) o[j][e] = 0.f;
    float mrow[2] = {-1e30f, -1e30f};
    float lrow[2] = {0.f, 0.f};

    for (int kt = 0; kt < nkt; kt++) {
        if (kt + 1 < nkt) {
            F_ISSUE((kt + 1) & 1, kt + 1);
            CP_COMMIT();
            CP_WAIT1();
        } else {
            CP_WAIT0();
        }
        __syncthreads();

        if (kt == 0) {
            #pragma unroll
            for (int ks = 0; ks < 4; ks++) {
                ldm4(qfh[ks], sb + a_off + ks * 32);
                ldm4(qfl[ks], sb + F_QL + a_off + ks * 32);
            }
        }

        const uint32_t stg = sb + F_STG + (uint32_t)(kt & 1) * F_STGB;

        float s[8][4];
        #pragma unroll
        for (int j = 0; j < 8; j++)
            #pragma unroll
            for (int e = 0; e < 4; e++) s[j][e] = 0.f;

        #pragma unroll
        for (int ks = 0; ks < 4; ks++) {
            #pragma unroll
            for (int g = 0; g < 4; g++) {
                uint32_t khf[4], klf[4];
                uint32_t off = bk_off + (uint32_t)g * 16 * FROWB + (uint32_t)ks * 32;
                ldm4(khf, stg + off);
                ldm4(klf, stg + 9216 + off);
                mma16816(s[2*g],   qfh[ks], khf[0], khf[1]);
                mma16816(s[2*g+1], qfh[ks], khf[2], khf[3]);
                mma16816(s[2*g],   qfh[ks], klf[0], klf[1]);
                mma16816(s[2*g+1], qfh[ks], klf[2], klf[3]);
                mma16816(s[2*g],   qfl[ks], khf[0], khf[1]);
                mma16816(s[2*g+1], qfl[ks], khf[2], khf[3]);
            }
        }

        if (kt >= 2 * qblk) {
            int qg0 = q0 + 16 * wid + (lane >> 2);
            int kgb = kt * 64 + (lane & 3) * 2;
            #pragma unroll
            for (int j = 0; j < 8; j++) {
                int kg = kgb + j * 8;
                if (kg     > qg0)     s[j][0] = -1e30f;
                if (kg + 1 > qg0)     s[j][1] = -1e30f;
                if (kg     > qg0 + 8) s[j][2] = -1e30f;
                if (kg + 1 > qg0 + 8) s[j][3] = -1e30f;
            }
        }

        float tm0 = -1e30f, tm1 = -1e30f;
        #pragma unroll
        for (int j = 0; j < 8; j++) {
            tm0 = fmaxf(tm0, fmaxf(s[j][0], s[j][1]));
            tm1 = fmaxf(tm1, fmaxf(s[j][2], s[j][3]));
        }
        tm0 = fmaxf(tm0, __shfl_xor_sync(0xffffffffu, tm0, 1));
        tm0 = fmaxf(tm0, __shfl_xor_sync(0xffffffffu, tm0, 2));
        tm1 = fmaxf(tm1, __shfl_xor_sync(0xffffffffu, tm1, 1));
        tm1 = fmaxf(tm1, __shfl_xor_sync(0xffffffffu, tm1, 2));
        float mn0 = fmaxf(mrow[0], tm0);
        float mn1 = fmaxf(mrow[1], tm1);
        float al0 = __expf(mrow[0] - mn0);
        float al1 = __expf(mrow[1] - mn1);
        float rs0 = 0.f, rs1 = 0.f;
        #pragma unroll
        for (int j = 0; j < 8; j++) {
            s[j][0] = __expf(s[j][0] - mn0);
            s[j][1] = __expf(s[j][1] - mn0);
            s[j][2] = __expf(s[j][2] - mn1);
            s[j][3] = __expf(s[j][3] - mn1);
            rs0 += s[j][0] + s[j][1];
            rs1 += s[j][2] + s[j][3];
        }
        rs0 += __shfl_xor_sync(0xffffffffu, rs0, 1);
        rs0 += __shfl_xor_sync(0xffffffffu, rs0, 2);
        rs1 += __shfl_xor_sync(0xffffffffu, rs1, 1);
        rs1 += __shfl_xor_sync(0xffffffffu, rs1, 2);
        lrow[0] = lrow[0] * al0 + rs0;
        lrow[1] = lrow[1] * al1 + rs1;
        mrow[0] = mn0;
        mrow[1] = mn1;
        #pragma unroll
        for (int j = 0; j < 8; j++) {
            o[j][0] *= al0; o[j][1] *= al0;
            o[j][2] *= al1; o[j][3] *= al1;
        }

        uint32_t pfh[4][4], pfl[4][4];
        #pragma unroll
        for (int ks = 0; ks < 4; ks++) {
            split2pack(s[2*ks][0],   s[2*ks][1],   pfh[ks][0], pfl[ks][0]);
            split2pack(s[2*ks][2],   s[2*ks][3],   pfh[ks][1], pfl[ks][1]);
            split2pack(s[2*ks+1][0], s[2*ks+1][1], pfh[ks][2], pfl[ks][2]);
            split2pack(s[2*ks+1][2], s[2*ks+1][3], pfh[ks][3], pfl[ks][3]);
        }

        #pragma unroll
        for (int ks = 0; ks < 4; ks++) {
            #pragma unroll
            for (int g = 0; g < 4; g++) {
                uint32_t vhf[4], vlf[4];
                uint32_t off = bv_off + (uint32_t)ks * 16 * FROWB + (uint32_t)g * 32;
                ldm4t(vhf, stg + 18432 + off);
                ldm4t(vlf, stg + 27648 + off);
                mma16816(o[2*g],   pfh[ks], vhf[0], vhf[1]);
                mma16816(o[2*g+1], pfh[ks], vhf[2], vhf[3]);
                mma16816(o[2*g],   pfh[ks], vlf[0], vlf[1]);
                mma16816(o[2*g+1], pfh[ks], vlf[2], vlf[3]);
                mma16816(o[2*g],   pfl[ks], vhf[0], vhf[1]);
                mma16816(o[2*g+1], pfl[ks], vhf[2], vhf[3]);
            }
        }
        __syncthreads();
    }
    #undef F_ISSUE

    float inv0 = 1.0f / lrow[0];
    float inv1 = 1.0f / lrow[1];
    int t0 = q0 + 16 * wid + (lane >> 2);
    int t1 = t0 + 8;
    #pragma unroll
    for (int j = 0; j < 8; j++) {
        int cb = j * 8 + (lane & 3) * 2;
        size_t e0 = rowbase + (size_t)t0 * Cc + cb;
        size_t e1 = rowbase + (size_t)t1 * Cc + cb;
        uint32_t hp, lp;
        split2pack(o[j][0] * inv0, o[j][1] * inv0, hp, lp);
        *(uint32_t*)(oh + e0) = hp;
        *(uint32_t*)(ol + e0) = lp;
        split2pack(o[j][2] * inv1, o[j][3] * inv1, hp, lp);
        *(uint32_t*)(oh + e1) = hp;
        *(uint32_t*)(ol + e1) = lp;
    }
}

// ---------------------------------------------------------------------------
__global__ void copy_kernel(const float4* __restrict__ src,
                            float4* __restrict__ dst, int n4)
{
    for (int i = blockIdx.x * blockDim.x + threadIdx.x; i < n4;
         i += gridDim.x * blockDim.x)
        dst[i] = src[i];
}

// ---------------------------------------------------------------------------
extern "C" void kernel_launch(void* const* d_in, const int* in_sizes, int n_in,
                              void* d_out, int out_size)
{
    const float *x, *v1, *Wq, *Wk, *Wv, *Wp, *lamb;
    if (in_sizes[0] == Mm * Cc) {            // dict order
        x    = (const float*)d_in[0];
        v1   = (const float*)d_in[1];
        Wq   = (const float*)d_in[2];
        Wk   = (const float*)d_in[3];
        Wv   = (const float*)d_in[4];
        Wp   = (const float*)d_in[5];
        lamb = (const float*)d_in[6];
    } else {                                  // alphabetical order
        Wk   = (const float*)d_in[0];
        Wp   = (const float*)d_in[1];
        Wq   = (const float*)d_in[2];
        Wv   = (const float*)d_in[3];
        lamb = (const float*)d_in[4];
        v1   = (const float*)d_in[5];
        x    = (const float*)d_in[6];
    }
    float* out = (float*)d_out;

    float *q, *k, *ctab, *stab;
    uint16_t *xh, *xl, *wh, *wl, *qhp, *qlp, *khp, *klp, *vhp, *vlp;
    cudaGetSymbolAddress((void**)&q,    g_q);
    cudaGetSymbolAddress((void**)&k,    g_k);
    cudaGetSymbolAddress((void**)&ctab, g_cos);
    cudaGetSymbolAddress((void**)&stab, g_sin);
    cudaGetSymbolAddress((void**)&xh,   g_xh);
    cudaGetSymbolAddress((void**)&xl,   g_xl);
    cudaGetSymbolAddress((void**)&wh,   g_wh);
    cudaGetSymbolAddress((void**)&wl,   g_wl);
    cudaGetSymbolAddress((void**)&qhp,  g_qh);
    cudaGetSymbolAddress((void**)&qlp,  g_ql);
    cudaGetSymbolAddress((void**)&khp,  g_kh);
    cudaGetSymbolAddress((void**)&klp,  g_kl);
    cudaGetSymbolAddress((void**)&vhp,  g_vh);
    cudaGetSymbolAddress((void**)&vlp,  g_vl);

    rope_table_kernel<<<Tt, 32>>>(ctab, stab);

    const int nx4 = Mm * Cc / 4;
    const int nw4 = Cc * Cc / 4;
    split_kernel<<<(nx4 + 255) / 256, 256>>>((const float4*)x,
        (uint2*)xh, (uint2*)xl, nx4);
    // weight order in g_wh/g_wl: [Wq, Wk, Wv, Wp]
    split_w_kernel<<<(4 * nw4 + 255) / 256, 256>>>(
        (const float4*)Wq, (const float4*)Wk, (const float4*)Wv,
        (const float4*)Wp, (uint2*)wh, (uint2*)wl, nw4);

    cudaFuncSetAttribute(gemm_qkv,
                         cudaFuncAttributeMaxDynamicSharedMemorySize, GBF_SMEM);
    cudaFuncSetAttribute(gemm_bf,
                         cudaFuncAttributeMaxDynamicSharedMemorySize, GBF_SMEM);

    gemm_qkv<<<dim3(Mm / 128, Cc / 128, 3), 256, GBF_SMEM>>>(
        xh, xl, wh, wl, q, k, v1, lamb, vhp, vlp);

    rmsrope_split<<<dim3(Bb * Tt * Hh / 8, 2), 256>>>(q, k, qhp, qlp, khp, klp,
                                                      ctab, stab);

    cudaFuncSetAttribute(flash_mma,
                         cudaFuncAttributeMaxDynamicSharedMemorySize, FLASH_SMEM);
    flash_mma<<<dim3(Tt / 128, Bb * Hh), 256, FLASH_SMEM>>>(
        qhp, qlp, khp, klp, vhp, vlp, xh, xl);

    gemm_bf<<<dim3(Mm / 128, Cc / 128), 256, GBF_SMEM>>>(
        xh, xl, wh + 3ll*Cc*Cc, wl + 3ll*Cc*Cc, out);

    if (out_size >= 2 * Mm * Cc)
        copy_kernel<<<2048, 256>>>((const float4*)v1,
                                   (float4*)(out + (size_t)Mm * Cc),
                                   (Mm * Cc) / 4);
}

// round 14
// speedup vs baseline: 3.7781x; 1.0988x over previous
#include <cuda_runtime.h>
#include <cuda_bf16.h>
#include <cstdint>
#include <math.h>

#define Bb 4
#define Tt 2048
#define Cc 1024
#define Hh 16
#define Dd 64
#define Mm (Bb*Tt)   /* 8192 rows */

// Scratch (device globals: allocation-free rule)
__device__ float g_q[Mm*Cc];
__device__ float g_k[Mm*Cc];
__device__ float g_cos[Tt*32];
__device__ float g_sin[Tt*32];
// bf16 hi/lo split operands
__device__ uint16_t g_xh[Mm*Cc];   // x split; later reused for attention output
__device__ uint16_t g_xl[Mm*Cc];
__device__ uint16_t g_wh[4*Cc*Cc];
__device__ uint16_t g_wl[4*Cc*Cc];
__device__ uint16_t g_qh[Mm*Cc];
__device__ uint16_t g_ql[Mm*Cc];
__device__ uint16_t g_kh[Mm*Cc];
__device__ uint16_t g_kl[Mm*Cc];
__device__ uint16_t g_vh[Mm*Cc];
__device__ uint16_t g_vl[Mm*Cc];

// ========================== helpers ===========================
__device__ __forceinline__ uint32_t smem_u32(const void* p)
{
    uint32_t a;
    asm("{ .reg .u64 t; cvta.to.shared.u64 t, %1; cvt.u32.u64 %0, t; }"
        : "=r"(a) : "l"(p));
    return a;
}

__device__ __forceinline__ void ldm4(uint32_t* r, uint32_t addr)
{
    asm volatile("ldmatrix.sync.aligned.m8n8.x4.shared.b16 {%0,%1,%2,%3}, [%4];"
                 : "=r"(r[0]), "=r"(r[1]), "=r"(r[2]), "=r"(r[3])
                 : "r"(addr));
}

__device__ __forceinline__ void ldm4t(uint32_t* r, uint32_t addr)
{
    asm volatile("ldmatrix.sync.aligned.m8n8.x4.trans.shared.b16 {%0,%1,%2,%3}, [%4];"
                 : "=r"(r[0]), "=r"(r[1]), "=r"(r[2]), "=r"(r[3])
                 : "r"(addr));
}

__device__ __forceinline__ void mma16816(float* d, const uint32_t* a,
                                         uint32_t b0, uint32_t b1)
{
    asm volatile(
        "mma.sync.aligned.m16n8k16.row.col.f32.bf16.bf16.f32 "
        "{%0,%1,%2,%3}, {%4,%5,%6,%7}, {%8,%9}, {%0,%1,%2,%3};"
        : "+f"(d[0]), "+f"(d[1]), "+f"(d[2]), "+f"(d[3])
        : "r"(a[0]), "r"(a[1]), "r"(a[2]), "r"(a[3]), "r"(b0), "r"(b1));
}

__device__ __forceinline__ void cp16(uint32_t dst, const void* src)
{
    asm volatile("cp.async.cg.shared.global [%0], [%1], 16;"
                 :: "r"(dst), "l"(src));
}
#define CP_COMMIT() asm volatile("cp.async.commit_group;" ::: "memory")
#define CP_WAIT1()  asm volatile("cp.async.wait_group 1;"  ::: "memory")
#define CP_WAIT0()  asm volatile("cp.async.wait_group 0;"  ::: "memory")

__device__ __forceinline__ void split4(float4 a, uint2& hi4, uint2& lo4)
{
    __nv_bfloat16 h0 = __float2bfloat16(a.x), h1 = __float2bfloat16(a.y);
    __nv_bfloat16 h2 = __float2bfloat16(a.z), h3 = __float2bfloat16(a.w);
    __nv_bfloat16 l0 = __float2bfloat16(a.x - __bfloat162float(h0));
    __nv_bfloat16 l1 = __float2bfloat16(a.y - __bfloat162float(h1));
    __nv_bfloat16 l2 = __float2bfloat16(a.z - __bfloat162float(h2));
    __nv_bfloat16 l3 = __float2bfloat16(a.w - __bfloat162float(h3));
    unsigned short u0 = *(unsigned short*)&h0, u1 = *(unsigned short*)&h1;
    unsigned short u2 = *(unsigned short*)&h2, u3 = *(unsigned short*)&h3;
    unsigned short v0 = *(unsigned short*)&l0, v1 = *(unsigned short*)&l1;
    unsigned short v2 = *(unsigned short*)&l2, v3 = *(unsigned short*)&l3;
    hi4.x = (uint32_t)u0 | ((uint32_t)u1 << 16);
    hi4.y = (uint32_t)u2 | ((uint32_t)u3 << 16);
    lo4.x = (uint32_t)v0 | ((uint32_t)v1 << 16);
    lo4.y = (uint32_t)v2 | ((uint32_t)v3 << 16);
}

__device__ __forceinline__ void split2pack(float x, float y,
                                           uint32_t& hp, uint32_t& lp)
{
    __nv_bfloat16 hx = __float2bfloat16(x), hy = __float2bfloat16(y);
    __nv_bfloat16 lx = __float2bfloat16(x - __bfloat162float(hx));
    __nv_bfloat16 ly = __float2bfloat16(y - __bfloat162float(hy));
    unsigned short a = *(unsigned short*)&hx, b = *(unsigned short*)&hy;
    unsigned short c = *(unsigned short*)&lx, d = *(unsigned short*)&ly;
    hp = (uint32_t)a | ((uint32_t)b << 16);
    lp = (uint32_t)c | ((uint32_t)d << 16);
}

// ---------------------------------------------------------------------------
// fp32 -> (hi, lo) bf16 split, elementwise.
// ---------------------------------------------------------------------------
__global__ void split_kernel(const float4* __restrict__ src,
                             uint2* __restrict__ hi, uint2* __restrict__ lo,
                             int n4)
{
    int i = blockIdx.x * blockDim.x + threadIdx.x;
    if (i < n4) {
        uint2 h4, l4;
        split4(src[i], h4, l4);
        hi[i] = h4;
        lo[i] = l4;
    }
}

// All four weights in one launch.
__global__ void split_w_kernel(const float4* __restrict__ w0,
                               const float4* __restrict__ w1,
                               const float4* __restrict__ w2,
                               const float4* __restrict__ w3,
                               uint2* __restrict__ hi, uint2* __restrict__ lo,
                               int n4each)
{
    int i = blockIdx.x * blockDim.x + threadIdx.x;
    if (i < 4 * n4each) {
        int w = i / n4each;
        int j = i - w * n4each;
        const float4* src = (w == 0) ? w0 : (w == 1) ? w1 : (w == 2) ? w2 : w3;
        uint2 h4, l4;
        split4(src[j], h4, l4);
        hi[i] = h4;
        lo[i] = l4;
    }
}

// ---------------------------------------------------------------------------
// Shared GEMM mainloop, 2-stage ring (issue AFTER compute; 2 CTAs/SM).
// Accumulates d[2][8][4] for a 128x128 tile of sum_k A[m][k]*W[n][k].
// ---------------------------------------------------------------------------
#define SK 40
#define ARR_B (128*SK*2)
#define STG_B (4*ARR_B)
#define NSTG 2
#define GBF_SMEM (NSTG*STG_B)    /* 81920 B -> 2 CTAs/SM */

#define ISSUE_STAGE(st, kb)                                                       \
    do {                                                                          \
        uint32_t sb_ = sbase + (uint32_t)(st) * STG_B;                            \
        int koff_ = (kb) * 32;                                                    \
        { int r_ = cr0;                                                           \
          uint32_t doff_ = (uint32_t)(r_ * 80 + cc0 * 16);                        \
          size_t ga_ = (size_t)(row0 + r_) * Cc + koff_ + cc0 * 8;                \
          size_t gw_ = (size_t)(col0 + r_) * Cc + koff_ + cc0 * 8;                \
          cp16(sb_ + doff_,             Ah + ga_);                                \
          cp16(sb_ + ARR_B + doff_,     Al + ga_);                                \
          cp16(sb_ + 2*ARR_B + doff_,   Wh + gw_);                                \
          cp16(sb_ + 3*ARR_B + doff_,   Wl + gw_); }                              \
        { int r_ = cr0 + 64;                                                      \
          uint32_t doff_ = (uint32_t)(r_ * 80 + cc0 * 16);                        \
          size_t ga_ = (size_t)(row0 + r_) * Cc + koff_ + cc0 * 8;                \
          size_t gw_ = (size_t)(col0 + r_) * Cc + koff_ + cc0 * 8;                \
          cp16(sb_ + doff_,             Ah + ga_);                                \
          cp16(sb_ + ARR_B + doff_,     Al + ga_);                                \
          cp16(sb_ + 2*ARR_B + doff_,   Wh + gw_);                                \
          cp16(sb_ + 3*ARR_B + doff_,   Wl + gw_); }                              \
    } while (0)

#define GEMM_MAINLOOP(Ah, Al, Wh, Wl, row0, col0)                                 \
    const uint32_t a_elem = (uint32_t)((warp_r*32 + (lane & 15)) * SK + (lane >> 4) * 8); \
    const uint32_t b_elem = (uint32_t)((warp_c*64 + (lane & 7) + ((lane >> 4) & 1) * 8) * SK \
                                       + ((lane >> 3) & 1) * 8);                  \
    const int cr0 = tid >> 2;                                                     \
    const int cc0 = tid & 3;                                                      \
    ISSUE_STAGE(0, 0); CP_COMMIT();                                               \
    ISSUE_STAGE(1, 1); CP_COMMIT();                                               \
    for (int kb = 0; kb < 32; kb++) {                                             \
        CP_WAIT1();                                                               \
        __syncthreads();                                                          \
        const uint32_t sb = sbase + (uint32_t)(kb & 1) * STG_B;                   \
        const uint32_t ah_b = sb;                                                 \
        const uint32_t al_b = sb + ARR_B;                                         \
        const uint32_t wh_b = sb + 2*ARR_B;                                       \
        const uint32_t wl_b = sb + 3*ARR_B;                                       \
        _Pragma("unroll")                                                         \
        for (int ks = 0; ks < 2; ks++) {                                          \
            uint32_t ahf[2][4], alf[2][4];                                        \
            _Pragma("unroll")                                                     \
            for (int mt = 0; mt < 2; mt++) {                                      \
                uint32_t off = 2u * (a_elem + (uint32_t)mt * 16 * SK + (uint32_t)ks * 16); \
                ldm4(ahf[mt], ah_b + off);                                        \
                ldm4(alf[mt], al_b + off);                                        \
            }                                                                     \
            uint32_t bh[4][4], bl[4][4];                                          \
            _Pragma("unroll")                                                     \
            for (int g = 0; g < 4; g++) {                                         \
                uint32_t off = 2u * (b_elem + (uint32_t)g * 16 * SK + (uint32_t)ks * 16); \
                ldm4(bh[g], wh_b + off);                                          \
                ldm4(bl[g], wl_b + off);                                          \
            }                                                                     \
            _Pragma("unroll")                                                     \
            for (int mt = 0; mt < 2; mt++) {                                      \
                _Pragma("unroll")                                                 \
                for (int g = 0; g < 4; g++) {                                     \
                    mma16816(d[mt][2*g],   ahf[mt], bh[g][0], bh[g][1]);          \
                    mma16816(d[mt][2*g+1], ahf[mt], bh[g][2], bh[g][3]);          \
                    mma16816(d[mt][2*g],   ahf[mt], bl[g][0], bl[g][1]);          \
                    mma16816(d[mt][2*g+1], ahf[mt], bl[g][2], bl[g][3]);          \
                    mma16816(d[mt][2*g],   alf[mt], bh[g][0], bh[g][1]);          \
                    mma16816(d[mt][2*g+1], alf[mt], bh[g][2], bh[g][3]);          \
                }                                                                 \
            }                                                                     \
        }                                                                         \
        __syncthreads();                                                          \
        if (kb + 2 < 32) {                                                        \
            ISSUE_STAGE(kb & 1, kb + 2);                                          \
            CP_COMMIT();                                                          \
        }                                                                         \
    }

// ---------------------------------------------------------------------------
// Fused QKV GEMM: gridDim.z selects {Wq->q fp32, Wk->k fp32, Wv->mix->vh/vl}.
// ---------------------------------------------------------------------------
__global__ __launch_bounds__(256, 2) void gemm_qkv(
    const uint16_t* __restrict__ Ah, const uint16_t* __restrict__ Al,
    const uint16_t* __restrict__ WhB, const uint16_t* __restrict__ WlB,
    float* __restrict__ qout, float* __restrict__ kout,
    const float* __restrict__ v1, const float* __restrict__ lambp,
    uint16_t* __restrict__ vhout, uint16_t* __restrict__ vlout)
{
    extern __shared__ __align__(16) char dsm[];
    const uint32_t sbase = smem_u32(dsm);
    const int tid  = threadIdx.x;
    const int wid  = tid >> 5;
    const int lane = tid & 31;
    const int warp_r = wid & 3;
    const int warp_c = wid >> 2;
    const int row0 = blockIdx.x * 128;
    const int col0 = blockIdx.y * 128;
    const int z = blockIdx.z;
    const uint16_t* Wh = WhB + (size_t)z * Cc * Cc;
    const uint16_t* Wl = WlB + (size_t)z * Cc * Cc;

    float d[2][8][4];
    #pragma unroll
    for (int mt = 0; mt < 2; mt++)
        #pragma unroll
        for (int nt = 0; nt < 8; nt++)
            #pragma unroll
            for (int e = 0; e < 4; e++) d[mt][nt][e] = 0.f;

    GEMM_MAINLOOP(Ah, Al, Wh, Wl, row0, col0)

    const int rbase = row0 + warp_r * 32 + (lane >> 2);
    const int cbase = col0 + warp_c * 64 + (lane & 3) * 2;
    if (z < 2) {
        float* Cout = z ? kout : qout;
        #pragma unroll
        for (int mt = 0; mt < 2; mt++) {
            #pragma unroll
            for (int nt = 0; nt < 8; nt++) {
                int rr = rbase + mt * 16;
                int cc = cbase + nt * 8;
                *(float2*)(Cout + (size_t)rr * Cc + cc) =
                    make_float2(d[mt][nt][0], d[mt][nt][1]);
                *(float2*)(Cout + (size_t)(rr + 8) * Cc + cc) =
                    make_float2(d[mt][nt][2], d[mt][nt][3]);
            }
        }
    } else {
        const float lam = *lambp;
        #pragma unroll
        for (int mt = 0; mt < 2; mt++) {
            #pragma unroll
            for (int nt = 0; nt < 8; nt++) {
                int rr = rbase + mt * 16;
                int cc = cbase + nt * 8;
                size_t e0 = (size_t)rr * Cc + cc;
                size_t e1 = (size_t)(rr + 8) * Cc + cc;
                float2 m0 = *(const float2*)(v1 + e0);
                float2 m1 = *(const float2*)(v1 + e1);
                float a0 = (1.f - lam) * d[mt][nt][0] + lam * m0.x;
                float a1 = (1.f - lam) * d[mt][nt][1] + lam * m0.y;
                float a2 = (1.f - lam) * d[mt][nt][2] + lam * m1.x;
                float a3 = (1.f - lam) * d[mt][nt][3] + lam * m1.y;
                uint32_t hp, lp;
                split2pack(a0, a1, hp, lp);
                *(uint32_t*)(vhout + e0) = hp;
                *(uint32_t*)(vlout + e0) = lp;
                split2pack(a2, a3, hp, lp);
                *(uint32_t*)(vhout + e1) = hp;
                *(uint32_t*)(vlout + e1) = lp;
            }
        }
    }
}

// ---------------------------------------------------------------------------
// Proj GEMM (fp32 out, no mix) — same mainloop.
// ---------------------------------------------------------------------------
__global__ __launch_bounds__(256, 2) void gemm_bf(
    const uint16_t* __restrict__ Ah, const uint16_t* __restrict__ Al,
    const uint16_t* __restrict__ Wh, const uint16_t* __restrict__ Wl,
    float* __restrict__ Cout)
{
    extern __shared__ __align__(16) char dsm[];
    const uint32_t sbase = smem_u32(dsm);
    const int tid  = threadIdx.x;
    const int wid  = tid >> 5;
    const int lane = tid & 31;
    const int warp_r = wid & 3;
    const int warp_c = wid >> 2;
    const int row0 = blockIdx.x * 128;
    const int col0 = blockIdx.y * 128;

    float d[2][8][4];
    #pragma unroll
    for (int mt = 0; mt < 2; mt++)
        #pragma unroll
        for (int nt = 0; nt < 8; nt++)
            #pragma unroll
            for (int e = 0; e < 4; e++) d[mt][nt][e] = 0.f;

    GEMM_MAINLOOP(Ah, Al, Wh, Wl, row0, col0)

    const int rbase = row0 + warp_r * 32 + (lane >> 2);
    const int cbase = col0 + warp_c * 64 + (lane & 3) * 2;
    #pragma unroll
    for (int mt = 0; mt < 2; mt++) {
        #pragma unroll
        for (int nt = 0; nt < 8; nt++) {
            int rr = rbase + mt * 16;
            int cc = cbase + nt * 8;
            *(float2*)(Cout + (size_t)rr * Cc + cc) =
                make_float2(d[mt][nt][0], d[mt][nt][1]);
            *(float2*)(Cout + (size_t)(rr + 8) * Cc + cc) =
                make_float2(d[mt][nt][2], d[mt][nt][3]);
        }
    }
}

// ---------------------------------------------------------------------------
// RoPE tables (fp64 trig; immune to --use_fast_math substitution).
// ---------------------------------------------------------------------------
__global__ void rope_table_kernel(float* __restrict__ ctab,
                                  float* __restrict__ stab)
{
    int t    = blockIdx.x;
    int lane = threadIdx.x;
    float invf = (float)exp2(-(double)lane * (13.287712379549449 / 32.0));
    float fr   = __fmul_rn((float)t, invf);
    ctab[t * 32 + lane] = (float)cos((double)fr);
    stab[t * 32 + lane] = (float)sin((double)fr);
}

// ---------------------------------------------------------------------------
// RMSNorm + RoPE, fp32 in -> hi/lo bf16 out (q pre-scaled by 0.125).
// ---------------------------------------------------------------------------
__global__ __launch_bounds__(256) void rmsrope_split(
    const float* __restrict__ qsrc, const float* __restrict__ ksrc,
    uint16_t* __restrict__ qh, uint16_t* __restrict__ ql,
    uint16_t* __restrict__ kh, uint16_t* __restrict__ kl,
    const float* __restrict__ ctab, const float* __restrict__ stab)
{
    const int isk = blockIdx.y;
    const float* src = isk ? ksrc : qsrc;
    uint16_t* dh = isk ? kh : qh;
    uint16_t* dl = isk ? kl : ql;
    const float scale = isk ? 1.0f : 0.125f;

    const int warp = threadIdx.x >> 5;
    const int lane = threadIdx.x & 31;
    const int row  = blockIdx.x * 8 + warp;
    const int t    = (row / Hh) % Tt;

    const float* base = src + (size_t)row * 64;
    float x1 = base[lane];
    float x2 = base[lane + 32];

    float ss = x1 * x1 + x2 * x2;
    #pragma unroll
    for (int off = 16; off; off >>= 1)
        ss += __shfl_xor_sync(0xffffffffu, ss, off);

    float r = rsqrtf(ss * (1.0f / 64.0f) + 1.1920929e-7f);
    float c = __ldg(&ctab[t * 32 + lane]);
    float s = __ldg(&stab[t * 32 + lane]);

    float n1 = x1 * r, n2 = x2 * r;
    float y1 = (n1 * c + n2 * s) * scale;
    float y2 = (n2 * c - n1 * s) * scale;

    size_t o = (size_t)row * 64;
    __nv_bfloat16 h1 = __float2bfloat16(y1);
    __nv_bfloat16 h2 = __float2bfloat16(y2);
    __nv_bfloat16 l1 = __float2bfloat16(y1 - __bfloat162float(h1));
    __nv_bfloat16 l2 = __float2bfloat16(y2 - __bfloat162float(h2));
    dh[o + lane]      = *(unsigned short*)&h1;
    dh[o + lane + 32] = *(unsigned short*)&h2;
    dl[o + lane]      = *(unsigned short*)&l1;
    dl[o + lane + 32] = *(unsigned short*)&l2;
}

// ---------------------------------------------------------------------------
// Flash attention on mma.sync (bf16 hi/lo split), causal (proven, R12).
// ---------------------------------------------------------------------------
#define FSK 72
#define FROWB (FSK*2)
#define F_QL 18432
#define F_STG 36864
#define F_STGB 36864
#define FLASH_SMEM (F_STG + 2*F_STGB)

__global__ __launch_bounds__(256, 1) void flash_mma(
    const uint16_t* __restrict__ qh, const uint16_t* __restrict__ ql,
    const uint16_t* __restrict__ kh, const uint16_t* __restrict__ kl,
    const uint16_t* __restrict__ vh, const uint16_t* __restrict__ vl,
    uint16_t* __restrict__ oh, uint16_t* __restrict__ ol)
{
    extern __shared__ __align__(16) char fsm[];
    const uint32_t sb = smem_u32(fsm);
    const int tid = threadIdx.x;
    const int wid = tid >> 5;
    const int lane = tid & 31;
    const int qblk = gridDim.x - 1 - blockIdx.x;
    const int bh = blockIdx.y;
    const int b = bh >> 4, h = bh & 15;
    const int q0 = qblk * 128;
    const int nkt = 2 * qblk + 2;
    const size_t rowbase = (size_t)b * Tt * Cc + (size_t)h * Dd;

    #define F_ISSUE(st, kt)                                                     \
    do {                                                                        \
        uint32_t s_ = sb + F_STG + (uint32_t)(st) * F_STGB;                     \
        int k0_ = (kt) * 64;                                                    \
        _Pragma("unroll")                                                       \
        for (int i_ = 0; i_ < 2; i_++) {                                        \
            int c_ = tid + 256 * i_;                                            \
            int r_ = c_ >> 3, cq_ = c_ & 7;                                     \
            size_t g_ = rowbase + (size_t)(k0_ + r_) * Cc + cq_ * 8;            \
            uint32_t d_ = s_ + (uint32_t)(r_ * FROWB + cq_ * 16);               \
            cp16(d_,         kh + g_);                                          \
            cp16(d_ +  9216, kl + g_);                                          \
            cp16(d_ + 18432, vh + g_);                                          \
            cp16(d_ + 27648, vl + g_);                                          \
        }                                                                       \
    } while (0)

    #pragma unroll
    for (int i = 0; i < 4; i++) {
        int c = tid + 256 * i;
        int r = c >> 3, cq = c & 7;
        size_t g = rowbase + (size_t)(q0 + r) * Cc + cq * 8;
        uint32_t d = sb + (uint32_t)(r * FROWB + cq * 16);
        cp16(d, qh + g);
        cp16(d + F_QL, ql + g);
    }
    F_ISSUE(0, 0);
    CP_COMMIT();

    const uint32_t a_off = (uint32_t)((16*wid + (lane & 15)) * FROWB + (lane >> 4) * 16);
    const uint32_t bk_off = (uint32_t)(((lane & 7) + ((lane >> 4) & 1) * 8) * FROWB
                                       + ((lane >> 3) & 1) * 16);
    const uint32_t bv_off = (uint32_t)(((lane & 7) + ((lane >> 3) & 1) * 8) * FROWB
                                       + ((lane >> 4) & 1) * 16);

    uint32_t qfh[4][4], qfl[4][4];
    float o[8][4];
    #pragma unroll
    for (int j = 0; j < 8; j++)
        #pragma unroll
        for (int e = 0; e < 4; e++) o[j][e] = 0.f;
    float mrow[2] = {-1e30f, -1e30f};
    float lrow[2] = {0.f, 0.f};

    for (int kt = 0; kt < nkt; kt++) {
        if (kt + 1 < nkt) {
            F_ISSUE((kt + 1) & 1, kt + 1);
            CP_COMMIT();
            CP_WAIT1();
        } else {
            CP_WAIT0();
        }
        __syncthreads();

        if (kt == 0) {
            #pragma unroll
            for (int ks = 0; ks < 4; ks++) {
                ldm4(qfh[ks], sb + a_off + ks * 32);
                ldm4(qfl[ks], sb + F_QL + a_off + ks * 32);
            }
        }

        const uint32_t stg = sb + F_STG + (uint32_t)(kt & 1) * F_STGB;

        float s[8][4];
        #pragma unroll
        for (int j = 0; j < 8; j++)
            #pragma unroll
            for (int e = 0; e < 4; e++) s[j][e] = 0.f;

        #pragma unroll
        for (int ks = 0; ks < 4; ks++) {
            #pragma unroll
            for (int g = 0; g < 4; g++) {
                uint32_t khf[4], klf[4];
                uint32_t off = bk_off + (uint32_t)g * 16 * FROWB + (uint32_t)ks * 32;
                ldm4(khf, stg + off);
                ldm4(klf, stg + 9216 + off);
                mma16816(s[2*g],   qfh[ks], khf[0], khf[1]);
                mma16816(s[2*g+1], qfh[ks], khf[2], khf[3]);
                mma16816(s[2*g],   qfh[ks], klf[0], klf[1]);
                mma16816(s[2*g+1], qfh[ks], klf[2], klf[3]);
                mma16816(s[2*g],   qfl[ks], khf[0], khf[1]);
                mma16816(s[2*g+1], qfl[ks], khf[2], khf[3]);
            }
        }

        if (kt >= 2 * qblk) {
            int qg0 = q0 + 16 * wid + (lane >> 2);
            int kgb = kt * 64 + (lane & 3) * 2;
            #pragma unroll
            for (int j = 0; j < 8; j++) {
                int kg = kgb + j * 8;
                if (kg     > qg0)     s[j][0] = -1e30f;
                if (kg + 1 > qg0)     s[j][1] = -1e30f;
                if (kg     > qg0 + 8) s[j][2] = -1e30f;
                if (kg + 1 > qg0 + 8) s[j][3] = -1e30f;
            }
        }

        float tm0 = -1e30f, tm1 = -1e30f;
        #pragma unroll
        for (int j = 0; j < 8; j++) {
            tm0 = fmaxf(tm0, fmaxf(s[j][0], s[j][1]));
            tm1 = fmaxf(tm1, fmaxf(s[j][2], s[j][3]));
        }
        tm0 = fmaxf(tm0, __shfl_xor_sync(0xffffffffu, tm0, 1));
        tm0 = fmaxf(tm0, __shfl_xor_sync(0xffffffffu, tm0, 2));
        tm1 = fmaxf(tm1, __shfl_xor_sync(0xffffffffu, tm1, 1));
        tm1 = fmaxf(tm1, __shfl_xor_sync(0xffffffffu, tm1, 2));
        float mn0 = fmaxf(mrow[0], tm0);
        float mn1 = fmaxf(mrow[1], tm1);
        float al0 = __expf(mrow[0] - mn0);
        float al1 = __expf(mrow[1] - mn1);
        float rs0 = 0.f, rs1 = 0.f;
        #pragma unroll
        for (int j = 0; j < 8; j++) {
            s[j][0] = __expf(s[j][0] - mn0);
            s[j][1] = __expf(s[j][1] - mn0);
            s[j][2] = __expf(s[j][2] - mn1);
            s[j][3] = __expf(s[j][3] - mn1);
            rs0 += s[j][0] + s[j][1];
            rs1 += s[j][2] + s[j][3];
        }
        rs0 += __shfl_xor_sync(0xffffffffu, rs0, 1);
        rs0 += __shfl_xor_sync(0xffffffffu, rs0, 2);
        rs1 += __shfl_xor_sync(0xffffffffu, rs1, 1);
        rs1 += __shfl_xor_sync(0xffffffffu, rs1, 2);
        lrow[0] = lrow[0] * al0 + rs0;
        lrow[1] = lrow[1] * al1 + rs1;
        mrow[0] = mn0;
        mrow[1] = mn1;
        #pragma unroll
        for (int j = 0; j < 8; j++) {
            o[j][0] *= al0; o[j][1] *= al0;
            o[j][2] *= al1; o[j][3] *= al1;
        }

        uint32_t pfh[4][4], pfl[4][4];
        #pragma unroll
        for (int ks = 0; ks < 4; ks++) {
            split2pack(s[2*ks][0],   s[2*ks][1],   pfh[ks][0], pfl[ks][0]);
            split2pack(s[2*ks][2],   s[2*ks][3],   pfh[ks][1], pfl[ks][1]);
            split2pack(s[2*ks+1][0], s[2*ks+1][1], pfh[ks][2], pfl[ks][2]);
            split2pack(s[2*ks+1][2], s[2*ks+1][3], pfh[ks][3], pfl[ks][3]);
        }

        #pragma unroll
        for (int ks = 0; ks < 4; ks++) {
            #pragma unroll
            for (int g = 0; g < 4; g++) {
                uint32_t vhf[4], vlf[4];
                uint32_t off = bv_off + (uint32_t)ks * 16 * FROWB + (uint32_t)g * 32;
                ldm4t(vhf, stg + 18432 + off);
                ldm4t(vlf, stg + 27648 + off);
                mma16816(o[2*g],   pfh[ks], vhf[0], vhf[1]);
                mma16816(o[2*g+1], pfh[ks], vhf[2], vhf[3]);
                mma16816(o[2*g],   pfh[ks], vlf[0], vlf[1]);
                mma16816(o[2*g+1], pfh[ks], vlf[2], vlf[3]);
                mma16816(o[2*g],   pfl[ks], vhf[0], vhf[1]);
                mma16816(o[2*g+1], pfl[ks], vhf[2], vhf[3]);
            }
        }
        __syncthreads();
    }
    #undef F_ISSUE

    float inv0 = 1.0f / lrow[0];
    float inv1 = 1.0f / lrow[1];
    int t0 = q0 + 16 * wid + (lane >> 2);
    int t1 = t0 + 8;
    #pragma unroll
    for (int j = 0; j < 8; j++) {
        int cb = j * 8 + (lane & 3) * 2;
        size_t e0 = rowbase + (size_t)t0 * Cc + cb;
        size_t e1 = rowbase + (size_t)t1 * Cc + cb;
        uint32_t hp, lp;
        split2pack(o[j][0] * inv0, o[j][1] * inv0, hp, lp);
        *(uint32_t*)(oh + e0) = hp;
        *(uint32_t*)(ol + e0) = lp;
        split2pack(o[j][2] * inv1, o[j][3] * inv1, hp, lp);
        *(uint32_t*)(oh + e1) = hp;
        *(uint32_t*)(ol + e1) = lp;
    }
}

// ---------------------------------------------------------------------------
__global__ void copy_kernel(const float4* __restrict__ src,
                            float4* __restrict__ dst, int n4)
{
    for (int i = blockIdx.x * blockDim.x + threadIdx.x; i < n4;
         i += gridDim.x * blockDim.x)
        dst[i] = src[i];
}

// ---------------------------------------------------------------------------
extern "C" void kernel_launch(void* const* d_in, const int* in_sizes, int n_in,
                              void* d_out, int out_size)
{
    const float *x, *v1, *Wq, *Wk, *Wv, *Wp, *lamb;
    if (in_sizes[0] == Mm * Cc) {            // dict order
        x    = (const float*)d_in[0];
        v1   = (const float*)d_in[1];
        Wq   = (const float*)d_in[2];
        Wk   = (const float*)d_in[3];
        Wv   = (const float*)d_in[4];
        Wp   = (const float*)d_in[5];
        lamb = (const float*)d_in[6];
    } else {                                  // alphabetical order
        Wk   = (const float*)d_in[0];
        Wp   = (const float*)d_in[1];
        Wq   = (const float*)d_in[2];
        Wv   = (const float*)d_in[3];
        lamb = (const float*)d_in[4];
        v1   = (const float*)d_in[5];
        x    = (const float*)d_in[6];
    }
    float* out = (float*)d_out;

    float *q, *k, *ctab, *stab;
    uint16_t *xh, *xl, *wh, *wl, *qhp, *qlp, *khp, *klp, *vhp, *vlp;
    cudaGetSymbolAddress((void**)&q,    g_q);
    cudaGetSymbolAddress((void**)&k,    g_k);
    cudaGetSymbolAddress((void**)&ctab, g_cos);
    cudaGetSymbolAddress((void**)&stab, g_sin);
    cudaGetSymbolAddress((void**)&xh,   g_xh);
    cudaGetSymbolAddress((void**)&xl,   g_xl);
    cudaGetSymbolAddress((void**)&wh,   g_wh);
    cudaGetSymbolAddress((void**)&wl,   g_wl);
    cudaGetSymbolAddress((void**)&qhp,  g_qh);
    cudaGetSymbolAddress((void**)&qlp,  g_ql);
    cudaGetSymbolAddress((void**)&khp,  g_kh);
    cudaGetSymbolAddress((void**)&klp,  g_kl);
    cudaGetSymbolAddress((void**)&vhp,  g_vh);
    cudaGetSymbolAddress((void**)&vlp,  g_vl);

    rope_table_kernel<<<Tt, 32>>>(ctab, stab);

    const int nx4 = Mm * Cc / 4;
    const int nw4 = Cc * Cc / 4;
    split_kernel<<<(nx4 + 255) / 256, 256>>>((const float4*)x,
        (uint2*)xh, (uint2*)xl, nx4);
    split_w_kernel<<<(4 * nw4 + 255) / 256, 256>>>(
        (const float4*)Wq, (const float4*)Wk, (const float4*)Wv,
        (const float4*)Wp, (uint2*)wh, (uint2*)wl, nw4);

    cudaFuncSetAttribute(gemm_qkv,
                         cudaFuncAttributeMaxDynamicSharedMemorySize, GBF_SMEM);
    cudaFuncSetAttribute(gemm_bf,
                         cudaFuncAttributeMaxDynamicSharedMemorySize, GBF_SMEM);

    gemm_qkv<<<dim3(Mm / 128, Cc / 128, 3), 256, GBF_SMEM>>>(
        xh, xl, wh, wl, q, k, v1, lamb, vhp, vlp);

    rmsrope_split<<<dim3(Bb * Tt * Hh / 8, 2), 256>>>(q, k, qhp, qlp, khp, klp,
                                                      ctab, stab);

    cudaFuncSetAttribute(flash_mma,
                         cudaFuncAttributeMaxDynamicSharedMemorySize, FLASH_SMEM);
    flash_mma<<<dim3(Tt / 128, Bb * Hh), 256, FLASH_SMEM>>>(
        qhp, qlp, khp, klp, vhp, vlp, xh, xl);

    gemm_bf<<<dim3(Mm / 128, Cc / 128), 256, GBF_SMEM>>>(
        xh, xl, wh + 3ll*Cc*Cc, wl + 3ll*Cc*Cc, out);

    if (out_size >= 2 * Mm * Cc)
        copy_kernel<<<2048, 256>>>((const float4*)v1,
                                   (float4*)(out + (size_t)Mm * Cc),
                                   (Mm * Cc) / 4);
}